// round 9
// baseline (speedup 1.0000x reference)
#include <cuda_runtime.h>
#include <cuda_fp16.h>
#include <cstdint>

// ---------------- problem constants ----------------
#define B_    32
#define L_    336
#define C_    321
#define P_    96
#define E_    4
#define H_    2048
#define PATCH 12
#define NROW  (B_*C_)          // 10272
#define KTOT  (E_*H_)          // 8192
#define INV_  0.99999499987499937f   // 1/sqrt(1+1e-5)

// ---------------- scratch (static device globals; no allocation) ----------------
__device__ float  g_h  [NROW*L_];
__device__ float  g_s2 [NROW*168];
__device__ float  g_s4 [NROW*84];
__device__ float  g_s8 [NROW*42];
__device__ float  g_t  [NROW*168];
__device__ float  g_cur[NROW*L_];
__device__ float  g_te [NROW*L_];
__device__ float  g_d  [NROW*L_];
__device__ __half g_ddih[NROW*L_];             // fp16 ddi (scan writes half)
__device__ __half g_w1h[E_*H_*L_];             // fp16 ew1 (5.5 MB)
__device__ float  g_gates[NROW*E_];
__device__ __half g_w2p[P_*KTOT];              // repacked fp16 ew2 [p][e*2048+h]

__device__ __forceinline__ float gelu_f(float x) {
    return 0.5f * x * (1.0f + erff(x * 0.70710678118654752f));
}

// ---------------- fp16 mma helpers ----------------
__device__ __forceinline__ void mma_f16(float* c, const uint32_t* a, const uint32_t* b) {
    asm volatile(
        "mma.sync.aligned.m16n8k16.row.col.f32.f16.f16.f32 "
        "{%0,%1,%2,%3}, {%4,%5,%6,%7}, {%8,%9}, {%0,%1,%2,%3};"
        : "+f"(c[0]), "+f"(c[1]), "+f"(c[2]), "+f"(c[3])
        : "r"(a[0]), "r"(a[1]), "r"(a[2]), "r"(a[3]), "r"(b[0]), "r"(b[1]));
}
__device__ __forceinline__ void ldsm_x4(uint32_t& r0, uint32_t& r1, uint32_t& r2, uint32_t& r3,
                                        uint32_t saddr) {
    asm volatile("ldmatrix.sync.aligned.m8n8.x4.shared.b16 {%0,%1,%2,%3}, [%4];"
                 : "=r"(r0), "=r"(r1), "=r"(r2), "=r"(r3) : "r"(saddr));
}
__device__ __forceinline__ uint32_t smem_u32(const void* p) {
    return (uint32_t)__cvta_generic_to_shared(p);
}
__device__ __forceinline__ void cp_async16(void* smem, const void* gmem) {
    uint32_t saddr = smem_u32(smem);
    asm volatile("cp.async.ca.shared.global [%0], [%1], 16;"
                 :: "r"(saddr), "l"(gmem));
}
__device__ __forceinline__ void cp_async16g(void* smem, const void* gmem, int bytes) {
    uint32_t saddr = smem_u32(smem);
    asm volatile("cp.async.ca.shared.global [%0], [%1], 16, %2;"
                 :: "r"(saddr), "l"(gmem), "r"(bytes));
}
__device__ __forceinline__ void cp_commit() { asm volatile("cp.async.commit_group;"); }
template<int N> __device__ __forceinline__ void cp_wait() {
    asm volatile("cp.async.wait_group %0;" :: "n"(N));
}

// ---------------- fp32 -> fp16 convert (elementwise) ----------------
__global__ void f2h_kernel(const float* __restrict__ in, __half* __restrict__ out, int n)
{
    int idx = blockIdx.x * blockDim.x + threadIdx.x;
    if (idx < n) out[idx] = __float2half_rn(in[idx]);
}

// ================= fused expert l1+l2 (fp16 m16n8k16, no g_hid) =================
// Grid (2, 81, 4): blockIdx.x = n-half (1024 cols), .y = 128-row block, .z = expert.
// For each of 8 chunks of 128 n-cols:
//   hc = half( gelu( A(128x336) @ W1c(128x336)^T + b1 ) )  -> smem
//   acc2(128x96) += hc @ W2c(96x128)^T
// Final: Out[b,p,c] += gate_e * (acc2 + (h==0 ? b2_e : 0))
// smem layout (dynamic, 163328 B):
//   As  : 128 x 352 halves  (90112 B)  @ 0
//   hc  : 128 x 136 halves  (34816 B)  @ 90112
//   w2s :  96 x 136 halves  (26112 B)  @ 124928
//   w1b : 2 x 128 x 24 halves (12288 B) @ 151040
__global__ void __launch_bounds__(256) expert_fused(
    const __half* __restrict__ A,      // NROW x 336
    const __half* __restrict__ W1,     // (E*2048) x 336
    const __half* __restrict__ W2,     // 96 x 8192
    const float* __restrict__ eb1,     // (E, 2048)
    const float* __restrict__ eb2,     // (E, 96)
    const float* __restrict__ gates,   // (NROW, 4)
    float* __restrict__ Out,           // (B, 96, C)
    int M)
{
    extern __shared__ char sm[];
    __half* As  = (__half*)(sm);
    __half* hc  = (__half*)(sm + 90112);
    __half* w2s = (__half*)(sm + 124928);
    __half* w1b = (__half*)(sm + 151040);

    int tid = threadIdx.x, lane = tid & 31, warp = tid >> 5;
    int h = blockIdx.x;
    int rowBase = blockIdx.y * 128;
    int e = blockIdx.z;
    int g = lane >> 2, t4 = lane & 3;
    int wm0 = (warp >> 1) * 32;
    int wn0 = (warp & 1) * 64;     // l1 n-split
    int wn2 = (warp & 1) * 48;     // l2 n-split

    uint32_t asB  = smem_u32(As);
    uint32_t hcB  = smem_u32(hc);
    uint32_t w2B  = smem_u32(w2s);
    uint32_t w1B  = smem_u32(w1b);

    uint32_t aOff1 = (uint32_t)(((wm0 + (lane & 15)) * 352 + ((lane >> 4) << 3)) * 2);
    uint32_t bOff1 = (uint32_t)(((wn0 + (lane & 7) + ((lane >> 4) << 3)) * 24
                                + (((lane >> 3) & 1) << 3)) * 2);
    uint32_t aOff2 = (uint32_t)(((wm0 + (lane & 15)) * 136 + ((lane >> 4) << 3)) * 2);
    uint32_t bOff2 = (uint32_t)(((wn2 + (lane & 7) + ((lane >> 4) << 3)) * 136
                                + (((lane >> 3) & 1) << 3)) * 2);

    // ---- load resident A tile (128 x 336), row stride 352 halves ----
    for (int i = tid; i < 128 * 42; i += 256) {
        int r = i / 42, c = i % 42;
        int gm = rowBase + r;
        int gmc = gm < M ? gm : (M - 1);
        cp_async16(As + r * 352 + c * 8, A + (size_t)gmc * L_ + c * 8);
    }
    cp_commit();
    cp_wait<0>();
    __syncthreads();

    float acc2[2][6][4];
    #pragma unroll
    for (int i = 0; i < 2; i++)
        #pragma unroll
        for (int j = 0; j < 6; j++)
            #pragma unroll
            for (int q = 0; q < 4; q++) acc2[i][j][q] = 0.f;

    const float* bias1 = eb1 + (size_t)e * H_;

    for (int nc = 0; nc < 8; nc++) {
        int nbase = h * 1024 + nc * 128;              // within expert H
        __syncthreads();   // previous iteration's readers of hc/w2s done

        // prefetch w2 chunk: 96 x 128 -> w2s (stride 136)
        {
            int wcol = e * H_ + nbase;
            for (int i = tid; i < 96 * 16; i += 256) {
                int r = i >> 4, c = i & 15;
                cp_async16(w2s + r * 136 + c * 8, W2 + (size_t)r * KTOT + wcol + c * 8);
            }
            cp_commit();
        }

        float acc[2][8][4];
        #pragma unroll
        for (int i = 0; i < 2; i++)
            #pragma unroll
            for (int j = 0; j < 8; j++)
                #pragma unroll
                for (int q = 0; q < 4; q++) acc[i][j][q] = 0.f;

        // W1 tile loader: rows = 128 n-cols of this chunk, k-slice 16
        auto loadW1 = [&](int it, int buf) {
            int r = tid >> 1, c = tid & 1;
            cp_async16(w1b + buf * 3072 + r * 24 + c * 8,
                       W1 + (size_t)(e * H_ + nbase + r) * L_ + it * 16 + c * 8);
            cp_commit();
        };

        int buf = 0;
        loadW1(0, 0);
        #pragma unroll 1
        for (int it = 0; it < 21; it++) {
            if (it + 1 < 21) { loadW1(it + 1, buf ^ 1); cp_wait<1>(); }
            else             { cp_wait<0>(); }
            __syncthreads();
            uint32_t afr[2][4], bfr[8][2];
            #pragma unroll
            for (int mt = 0; mt < 2; mt++)
                ldsm_x4(afr[mt][0], afr[mt][1], afr[mt][2], afr[mt][3],
                        asB + aOff1 + (uint32_t)(mt * 11264 + it * 32));
            #pragma unroll
            for (int np = 0; np < 4; np++)
                ldsm_x4(bfr[2 * np][0], bfr[2 * np][1], bfr[2 * np + 1][0], bfr[2 * np + 1][1],
                        w1B + (uint32_t)(buf * 6144) + bOff1 + (uint32_t)(np * 768));
            #pragma unroll
            for (int mt = 0; mt < 2; mt++)
                #pragma unroll
                for (int nt = 0; nt < 8; nt++)
                    mma_f16(acc[mt][nt], afr[mt], bfr[nt]);
            __syncthreads();
            buf ^= 1;
        }

        // l1 epilogue -> hc (fp16), same rounding as before
        #pragma unroll
        for (int mt = 0; mt < 2; mt++) {
            int r0l = wm0 + mt * 16 + g;
            int r1l = r0l + 8;
            #pragma unroll
            for (int nt = 0; nt < 8; nt++) {
                int cl = wn0 + nt * 8 + 2 * t4;
                float b0 = bias1[nbase + cl], b1v = bias1[nbase + cl + 1];
                *(__half2*)(hc + r0l * 136 + cl) =
                    __floats2half2_rn(gelu_f(acc[mt][nt][0] + b0),
                                      gelu_f(acc[mt][nt][1] + b1v));
                *(__half2*)(hc + r1l * 136 + cl) =
                    __floats2half2_rn(gelu_f(acc[mt][nt][2] + b0),
                                      gelu_f(acc[mt][nt][3] + b1v));
            }
        }
        __syncthreads();   // hc + w2s ready (w2 cp group drained by wait<0> above)

        // l2: acc2 += hc(128x128) @ w2s(96x128)^T, all smem
        #pragma unroll
        for (int it2 = 0; it2 < 8; it2++) {
            uint32_t afr[2][4], bfr[6][2];
            #pragma unroll
            for (int mt = 0; mt < 2; mt++)
                ldsm_x4(afr[mt][0], afr[mt][1], afr[mt][2], afr[mt][3],
                        hcB + aOff2 + (uint32_t)(mt * 4352 + it2 * 32));
            #pragma unroll
            for (int np = 0; np < 3; np++)
                ldsm_x4(bfr[2 * np][0], bfr[2 * np][1], bfr[2 * np + 1][0], bfr[2 * np + 1][1],
                        w2B + bOff2 + (uint32_t)(np * 4352 + it2 * 32));
            #pragma unroll
            for (int mt = 0; mt < 2; mt++)
                #pragma unroll
                for (int nt = 0; nt < 6; nt++)
                    mma_f16(acc2[mt][nt], afr[mt], bfr[nt]);
        }
    }

    // final epilogue: gate scale (+ gated b2 once, on h==0), atomicAdd to (B,96,C)
    #pragma unroll
    for (int mt = 0; mt < 2; mt++) {
        #pragma unroll
        for (int hh = 0; hh < 2; hh++) {
            int gm = rowBase + wm0 + mt * 16 + g + hh * 8;
            if (gm >= M) continue;
            float gate = gates[gm * 4 + e];
            int bb = gm / C_, cc = gm % C_;
            #pragma unroll
            for (int nt = 0; nt < 6; nt++) {
                int c0 = wn2 + nt * 8 + 2 * t4;
                #pragma unroll
                for (int q = 0; q < 2; q++) {
                    int gn = c0 + q;
                    float v = acc2[mt][nt][hh * 2 + q];
                    if (h == 0) v += eb2[e * P_ + gn];
                    atomicAdd(&Out[((size_t)bb * P_ + gn) * C_ + cc], gate * v);
                }
            }
        }
    }
}

// ---------------- bn + transpose: x (B,L,C) -> h (B,C,L) with mdm_bn ----------------
__global__ void bn_transpose_kernel(const float* __restrict__ x,
                                    const float* __restrict__ w,
                                    const float* __restrict__ b,
                                    float* __restrict__ h)
{
    __shared__ float tile[32][33];
    int bi = blockIdx.z;
    int l0 = blockIdx.x * 32;
    int c0 = blockIdx.y * 32;
    int tx = threadIdx.x, ty = threadIdx.y;   // 32 x 8
    #pragma unroll
    for (int i = 0; i < 32; i += 8) {
        int l = l0 + ty + i, c = c0 + tx;
        tile[ty + i][tx] = (l < L_ && c < C_) ? x[((size_t)bi * L_ + l) * C_ + c] : 0.f;
    }
    __syncthreads();
    #pragma unroll
    for (int i = 0; i < 32; i += 8) {
        int c = c0 + ty + i, l = l0 + tx;
        if (c < C_ && l < L_) {
            float v = tile[tx][ty + i];
            int wi = c * L_ + l;
            h[((size_t)bi * C_ + c) * L_ + l] = v * (w[wi] * INV_) + b[wi];
        }
    }
}

// ---------------- avg-pool by 2 along last dim ----------------
__global__ void pool2_kernel(const float* __restrict__ in, float* __restrict__ out, int Lout)
{
    int idx = blockIdx.x * blockDim.x + threadIdx.x;
    int total = NROW * Lout;
    if (idx >= total) return;
    int r = idx / Lout, j = idx % Lout;
    const float* p = in + (size_t)r * 2 * Lout + 2 * j;
    out[idx] = 0.5f * (p[0] + p[1]);
}

// ---------------- mixer fp32 GEMM, small-BM for occupancy ----------------
template<int ACT, int BM, int TM>
__global__ void __launch_bounds__(256) gemm_a(
    const float* __restrict__ A, int lda,
    const float* __restrict__ W,
    const float* __restrict__ bias,
    const float* __restrict__ resid,
    float* __restrict__ Cout, int ldc,
    int M, int N, int K)
{
    constexpr int BN = 128, BK = 16, TN = 8;
    __shared__ __align__(16) float As[BK][BM + 4];
    __shared__ __align__(16) float Ws[BK][BN + 4];
    int tid = threadIdx.x;
    int ty = tid >> 4, tx = tid & 15;          // ty 0..15 -> rows ty*TM; tx -> cols tx*8
    int rowBase = blockIdx.y * BM, colBase = blockIdx.x * BN;
    float acc[TM][TN] = {};

    for (int k0 = 0; k0 < K; k0 += BK) {
        for (int i = tid; i < BM * BK; i += 256) {
            int m = i / BK, kk = i % BK;
            int gk = k0 + kk;
            int gm = rowBase + m;
            As[kk][m] = (gm < M && gk < K) ? A[(size_t)gm * lda + gk] : 0.f;
        }
        for (int i = tid; i < BN * BK; i += 256) {
            int m = i / BK, kk = i % BK;
            int gk = k0 + kk;
            int gn = colBase + m;
            Ws[kk][m] = (gn < N && gk < K) ? W[(size_t)gn * K + gk] : 0.f;
        }
        __syncthreads();
        #pragma unroll
        for (int kk = 0; kk < BK; kk++) {
            float a[TM], bf[TN];
            #pragma unroll
            for (int i = 0; i < TM; i++) a[i] = As[kk][ty * TM + i];
            *(float4*)&bf[0] = *(const float4*)&Ws[kk][tx * TN];
            *(float4*)&bf[4] = *(const float4*)&Ws[kk][tx * TN + 4];
            #pragma unroll
            for (int i = 0; i < TM; i++)
                #pragma unroll
                for (int j = 0; j < TN; j++)
                    acc[i][j] += a[i] * bf[j];
        }
        __syncthreads();
    }

    #pragma unroll
    for (int i = 0; i < TM; i++) {
        int gm = rowBase + ty * TM + i;
        if (gm >= M) continue;
        #pragma unroll
        for (int j = 0; j < TN; j++) {
            int gn = colBase + tx * TN + j;
            if (gn >= N) continue;
            float v = acc[i][j] + (bias ? bias[gn] : 0.f);
            if (ACT == 1) v = gelu_f(v);
            if (resid) v += resid[(size_t)gm * N + gn];
            Cout[(size_t)gm * ldc + gn] = v;
        }
    }
}

// ---------------- gating ----------------
__global__ void gate_kernel(const float* __restrict__ te,
                            const float* __restrict__ gw,
                            const float* __restrict__ gb,
                            float* __restrict__ gates)
{
    int warp = (blockIdx.x * blockDim.x + threadIdx.x) >> 5;
    int lane = threadIdx.x & 31;
    if (warp >= NROW) return;
    const float* row = te + (size_t)warp * L_;
    float acc[E_] = {0.f, 0.f, 0.f, 0.f};
    for (int l = lane; l < L_; l += 32) {
        float xv = row[l];
        #pragma unroll
        for (int e = 0; e < E_; e++) acc[e] += xv * gw[e * L_ + l];
    }
    #pragma unroll
    for (int off = 16; off; off >>= 1)
        #pragma unroll
        for (int e = 0; e < E_; e++)
            acc[e] += __shfl_xor_sync(0xffffffffu, acc[e], off);
    if (lane == 0) {
        float lg[E_], arr[E_];
        #pragma unroll
        for (int e = 0; e < E_; e++) { lg[e] = acc[e] + gb[e]; arr[e] = lg[e]; }
        #pragma unroll
        for (int i = 0; i < 3; i++)
            #pragma unroll
            for (int j = 0; j < 3; j++)
                if (arr[j] > arr[j + 1]) { float tmp = arr[j]; arr[j] = arr[j + 1]; arr[j + 1] = tmp; }
        float kth = arr[E_ - 2];
        float mx = lg[0];
        #pragma unroll
        for (int e = 1; e < E_; e++) mx = fmaxf(mx, lg[e]);
        float s[E_], ssum = 0.f;
        #pragma unroll
        for (int e = 0; e < E_; e++) { s[e] = expf(lg[e] - mx); ssum += s[e]; }
        #pragma unroll
        for (int e = 0; e < E_; e++) s[e] /= ssum;
        float dec[E_];
        #pragma unroll
        for (int e = 0; e < E_; e++)
            dec[e] = (lg[e] < kth) ? 10.f * logf(s[e] + 1.f) : 10.f * (expf(s[e]) - 1.f);
        float m2 = dec[0];
        #pragma unroll
        for (int e = 1; e < E_; e++) m2 = fmaxf(m2, dec[e]);
        float t2[E_], su = 0.f;
        #pragma unroll
        for (int e = 0; e < E_; e++) { t2[e] = expf(dec[e] - m2); su += t2[e]; }
        #pragma unroll
        for (int e = 0; e < E_; e++) gates[(size_t)warp * E_ + e] = t2[e] / su;
    }
}

// ---------------- ddi bn ----------------
__global__ void bn_ddi_kernel(const float* __restrict__ te,
                              const float* __restrict__ w,
                              const float* __restrict__ b,
                              float* __restrict__ out)
{
    int idx = blockIdx.x * blockDim.x + threadIdx.x;
    if (idx >= NROW * L_) return;
    int l = idx % L_;
    int c = (idx / L_) % C_;
    int wi = c * L_ + l;
    out[idx] = te[idx] * (w[wi] * INV_) + b[wi];
}

// ---------------- ddi sequential scan (writes fp16 output) ----------------
__global__ void ddi_scan_kernel(const float* __restrict__ d,
                                const float* __restrict__ n1w,
                                const float* __restrict__ n1b,
                                const float* __restrict__ agg_w,
                                const float* __restrict__ agg_b,
                                __half* __restrict__ out)
{
    __shared__ float aw[PATCH * PATCH];
    __shared__ float ab[PATCH];
    for (int i = threadIdx.x; i < PATCH * PATCH; i += blockDim.x) aw[i] = agg_w[i];
    for (int i = threadIdx.x; i < PATCH; i += blockDim.x) ab[i] = agg_b[i];
    __syncthreads();
    int row = blockIdx.x * blockDim.x + threadIdx.x;
    if (row >= NROW) return;
    int c = row % C_;
    float w[PATCH], bb[PATCH], prev[PATCH];
    #pragma unroll
    for (int p = 0; p < PATCH; p++) {
        w[p]  = n1w[c * PATCH + p] * INV_;
        bb[p] = n1b[c * PATCH + p];
    }
    const float* drow = d + (size_t)row * L_;
    __half* orow = out + (size_t)row * L_;
    #pragma unroll
    for (int p = 0; p < PATCH; p++) {
        prev[p] = drow[p];
        orow[p] = __float2half_rn(prev[p]);
    }
    for (int t = 1; t < L_ / PATCH; t++) {
        float inp[PATCH], tmp[PATCH];
        #pragma unroll
        for (int p = 0; p < PATCH; p++) inp[p] = prev[p] * w[p] + bb[p];
        #pragma unroll
        for (int m = 0; m < PATCH; m++) {
            float s = ab[m];
            #pragma unroll
            for (int p = 0; p < PATCH; p++) s += inp[p] * aw[m * PATCH + p];
            tmp[m] = gelu_f(s);
        }
        #pragma unroll
        for (int p = 0; p < PATCH; p++) {
            prev[p] = tmp[p] + drow[t * PATCH + p];
            orow[t * PATCH + p] = __float2half_rn(prev[p]);
        }
    }
}

// ---------------- repack ew2 (E,P,H) -> (P, E*H), fp16 ----------------
__global__ void repack_w2_kernel(const float* __restrict__ ew2, __half* __restrict__ w2p)
{
    int idx = blockIdx.x * blockDim.x + threadIdx.x;
    if (idx >= P_ * KTOT) return;
    int p = idx / KTOT;
    int r = idx % KTOT;
    int e = r / H_, hh = r % H_;
    w2p[idx] = __float2half_rn(ew2[((size_t)e * P_ + p) * H_ + hh]);
}

__global__ void zero_kernel(float* o, int n)
{
    int idx = blockIdx.x * blockDim.x + threadIdx.x;
    if (idx < n) o[idx] = 0.f;
}

// ---------------- launch ----------------
extern "C" void kernel_launch(void* const* d_in, const int* in_sizes, int n_in,
                              void* d_out, int out_size)
{
    // Map inputs, skipping the scalar 'k' (size 1) wherever it sits.
    const float* in[27];
    int pi = 0;
    for (int i = 0; i < n_in && pi < 27; i++) {
        if (in_sizes[i] == 1) continue;
        in[pi++] = (const float*)d_in[i];
    }
    const float* x    = in[0];
    const float* mdw  = in[1];  const float* mdb  = in[2];
    const float* w1s[3] = { in[3], in[7],  in[11] };
    const float* b1s[3] = { in[4], in[8],  in[12] };
    const float* w2s[3] = { in[5], in[9],  in[13] };
    const float* b2s[3] = { in[6], in[10], in[14] };
    const float* ddw  = in[15]; const float* ddb  = in[16];
    const float* n1w  = in[17]; const float* n1b  = in[18];
    const float* aggw = in[19]; const float* aggb = in[20];
    const float* gw   = in[21]; const float* gb   = in[22];
    const float* ew1  = in[23]; const float* eb1  = in[24];
    const float* ew2  = in[25]; const float* eb2  = in[26];

    float *h, *s2, *s4, *s8, *t, *cur, *te, *dd, *gates;
    __half *ddih, *w1h, *w2p;
    cudaGetSymbolAddress((void**)&h,    g_h);
    cudaGetSymbolAddress((void**)&s2,   g_s2);
    cudaGetSymbolAddress((void**)&s4,   g_s4);
    cudaGetSymbolAddress((void**)&s8,   g_s8);
    cudaGetSymbolAddress((void**)&t,    g_t);
    cudaGetSymbolAddress((void**)&cur,  g_cur);
    cudaGetSymbolAddress((void**)&te,   g_te);
    cudaGetSymbolAddress((void**)&dd,   g_d);
    cudaGetSymbolAddress((void**)&ddih, g_ddih);
    cudaGetSymbolAddress((void**)&w1h,  g_w1h);
    cudaGetSymbolAddress((void**)&gates,g_gates);
    cudaGetSymbolAddress((void**)&w2p,  g_w2p);

    float* out = (float*)d_out;

    // 1) bn + transpose -> h (B,C,L)
    {
        dim3 tb(32, 8);
        dim3 tg((L_ + 31) / 32, (C_ + 31) / 32, B_);
        bn_transpose_kernel<<<tg, tb>>>(x, mdw, mdb, h);
    }
    // 2) pools
    pool2_kernel<<<(NROW * 168 + 255) / 256, 256>>>(h,  s2, 168);
    pool2_kernel<<<(NROW * 84  + 255) / 256, 256>>>(s2, s4, 84);
    pool2_kernel<<<(NROW * 42  + 255) / 256, 256>>>(s4, s8, 42);

    // 3) mixer stages (fp32, BM=32 tiles for occupancy)
    auto mgrid = [](int M, int N) { return dim3((N + 127) / 128, (M + 31) / 32); };
    gemm_a<1,32,2><<<mgrid(NROW, 42), 256>>>(s8, 42, w1s[0], b1s[0], nullptr, t,   42,  NROW, 42,  42);
    gemm_a<0,32,2><<<mgrid(NROW, 84), 256>>>(t,  42, w2s[0], b2s[0], s4,      cur, 84,  NROW, 84,  42);
    gemm_a<1,32,2><<<mgrid(NROW, 84), 256>>>(cur,84, w1s[1], b1s[1], nullptr, t,   84,  NROW, 84,  84);
    gemm_a<0,32,2><<<mgrid(NROW,168), 256>>>(t,  84, w2s[1], b2s[1], s2,      cur, 168, NROW, 168, 84);
    gemm_a<1,32,2><<<mgrid(NROW,168), 256>>>(cur,168,w1s[2], b1s[2], nullptr, t,   168, NROW, 168, 168);
    gemm_a<0,32,2><<<mgrid(NROW,336), 256>>>(t,  168,w2s[2], b2s[2], h,       te,  336, NROW, 336, 168);

    // 4) gating from te
    gate_kernel<<<(NROW * 32 + 255) / 256, 256>>>(te, gw, gb, gates);

    // 5) ddi: bn then 27-step scan (scan emits fp16 ddi directly)
    bn_ddi_kernel<<<(NROW * L_ + 255) / 256, 256>>>(te, ddw, ddb, dd);
    ddi_scan_kernel<<<(NROW + 127) / 128, 128>>>(dd, n1w, n1b, aggw, aggb, ddih);

    // 6) convert expert weights to fp16
    f2h_kernel<<<(E_ * H_ * L_ + 255) / 256, 256>>>(ew1, w1h, E_ * H_ * L_);
    repack_w2_kernel<<<(P_ * KTOT + 255) / 256, 256>>>(ew2, w2p);
    zero_kernel<<<(out_size + 255) / 256, 256>>>(out, out_size);

    // 7) fused experts (l1+l2, no hid round-trip)
    {
        const int smem_bytes = 163328;
        cudaFuncSetAttribute(expert_fused,
                             cudaFuncAttributeMaxDynamicSharedMemorySize, smem_bytes);
        dim3 tg(2, (NROW + 127) / 128, E_);
        expert_fused<<<tg, 256, smem_bytes>>>(ddih, w1h, w2p, eb1, eb2, gates, out, NROW);
    }
}

// round 10
// speedup vs baseline: 1.2255x; 1.2255x over previous
#include <cuda_runtime.h>
#include <cuda_fp16.h>
#include <cstdint>

// ---------------- problem constants ----------------
#define B_    32
#define L_    336
#define C_    321
#define P_    96
#define E_    4
#define H_    2048
#define PATCH 12
#define NROW  (B_*C_)          // 10272
#define KTOT  (E_*H_)          // 8192
#define INV_  0.99999499987499937f   // 1/sqrt(1+1e-5)

// ---------------- scratch (static device globals; no allocation) ----------------
__device__ float  g_h  [NROW*L_];
__device__ float  g_s2 [NROW*168];
__device__ float  g_s4 [NROW*84];
__device__ float  g_s8 [NROW*42];
__device__ float  g_t  [NROW*168];
__device__ float  g_cur[NROW*L_];
__device__ float  g_te [NROW*L_];
__device__ float  g_d  [NROW*L_];
__device__ __half g_ddih[NROW*L_];             // fp16 ddi (scan writes half)
__device__ __half g_w1h[E_*H_*L_];             // fp16 ew1 (5.5 MB)
__device__ float  g_gates[NROW*E_];
__device__ __half g_hid[(size_t)NROW*KTOT];    // 168 MB fp16
__device__ __half g_w2p[P_*KTOT];              // repacked fp16 ew2

__device__ __forceinline__ float gelu_f(float x) {
    return 0.5f * x * (1.0f + erff(x * 0.70710678118654752f));
}

// ---------------- fp16 mma helpers ----------------
__device__ __forceinline__ void mma_f16(float* c, const uint32_t* a, const uint32_t* b) {
    asm volatile(
        "mma.sync.aligned.m16n8k16.row.col.f32.f16.f16.f32 "
        "{%0,%1,%2,%3}, {%4,%5,%6,%7}, {%8,%9}, {%0,%1,%2,%3};"
        : "+f"(c[0]), "+f"(c[1]), "+f"(c[2]), "+f"(c[3])
        : "r"(a[0]), "r"(a[1]), "r"(a[2]), "r"(a[3]), "r"(b[0]), "r"(b[1]));
}
__device__ __forceinline__ void ldsm_x4(uint32_t& r0, uint32_t& r1, uint32_t& r2, uint32_t& r3,
                                        uint32_t saddr) {
    asm volatile("ldmatrix.sync.aligned.m8n8.x4.shared.b16 {%0,%1,%2,%3}, [%4];"
                 : "=r"(r0), "=r"(r1), "=r"(r2), "=r"(r3) : "r"(saddr));
}
__device__ __forceinline__ uint32_t smem_u32(const void* p) {
    return (uint32_t)__cvta_generic_to_shared(p);
}
__device__ __forceinline__ void cp_async16g(void* smem, const void* gmem, int bytes) {
    uint32_t saddr = smem_u32(smem);
    asm volatile("cp.async.ca.shared.global [%0], [%1], 16, %2;"
                 :: "r"(saddr), "l"(gmem), "r"(bytes));
}
__device__ __forceinline__ void cp_commit() { asm volatile("cp.async.commit_group;"); }
template<int N> __device__ __forceinline__ void cp_wait() {
    asm volatile("cp.async.wait_group %0;" :: "n"(N));
}

// ---------------- fp32 -> fp16 convert (elementwise) ----------------
__global__ void f2h_kernel(const float* __restrict__ in, __half* __restrict__ out, int n)
{
    int idx = blockIdx.x * blockDim.x + threadIdx.x;
    if (idx < n) out[idx] = __float2half_rn(in[idx]);
}

// ================= expert layer-1: fp16 m16n8k16 GEMM, BK=32 =================
// hid[row, e*H + n] = half( gates[row,e] * gelu( A[row,:336] @ W_e[n,:336]^T + eb1_e[n] ) )
// BM=128, BN=128, BK=32 (K padded 336->352 with zeros), 8 warps 4x2, warp tile 32x64.
__global__ void __launch_bounds__(256) gemm_f16_l1(
    const __half* __restrict__ A,     // NROW x 336
    const __half* __restrict__ W1,    // (E, 2048, 336)
    const float* __restrict__ eb1,    // (E, 2048)
    const float* __restrict__ gates,  // (NROW, 4)
    __half* __restrict__ hid,         // NROW x 8192
    int M)
{
    constexpr int KK = L_;            // 336
    constexpr int NK = 11;            // 11 * 32 = 352 (zero-padded)
    __shared__ __align__(16) __half As[2][128][40];
    __shared__ __align__(16) __half Ws[2][128][40];

    int tid = threadIdx.x;
    int e   = blockIdx.z;
    const __half* W   = W1 + (size_t)e * H_ * KK;
    const float* bias = eb1 + (size_t)e * H_;
    int rowBase = blockIdx.y * 128;
    int colBase = blockIdx.x * 128;
    int lane = tid & 31, warp = tid >> 5;
    int g = lane >> 2, t4 = lane & 3;
    int wm0 = (warp >> 1) * 32, wn0 = (warp & 1) * 64;

    uint32_t aBase[2] = { smem_u32(&As[0][0][0]), smem_u32(&As[1][0][0]) };
    uint32_t bBase[2] = { smem_u32(&Ws[0][0][0]), smem_u32(&Ws[1][0][0]) };
    uint32_t aOff = (uint32_t)(((wm0 + (lane & 15)) * 40 + ((lane >> 4) << 3)) * 2);
    uint32_t bOff = (uint32_t)(((wn0 + (lane & 7) + ((lane >> 4) << 3)) * 40
                               + (((lane >> 3) & 1) << 3)) * 2);

    float acc[2][8][4];
    #pragma unroll
    for (int i = 0; i < 2; i++)
        #pragma unroll
        for (int j = 0; j < 8; j++)
            #pragma unroll
            for (int q = 0; q < 4; q++) acc[i][j][q] = 0.f;

    auto load_tile = [&](int it, int buf) {
        int k0 = it * 32;
        #pragma unroll
        for (int j = 0; j < 2; j++) {
            int i = tid + 256 * j;            // 0..511
            int r = i >> 2, c = i & 3;        // 128 rows x 4 chunks of 8 halves
            int kf = k0 + c * 8;
            int kfc = kf < KK ? kf : 0;
            int gm = rowBase + r;
            int gmc = gm < M ? gm : (M - 1);
            cp_async16g(&As[buf][r][c * 8],
                        A + (size_t)gmc * KK + kfc,
                        (gm < M && kf < KK) ? 16 : 0);
            cp_async16g(&Ws[buf][r][c * 8],
                        W + (size_t)(colBase + r) * KK + kfc,
                        (kf < KK) ? 16 : 0);
        }
    };

    int buf = 0;
    load_tile(0, 0); cp_commit();
    for (int it = 0; it < NK; it++) {
        if (it + 1 < NK) { load_tile(it + 1, buf ^ 1); cp_commit(); cp_wait<1>(); }
        else             { cp_wait<0>(); }
        __syncthreads();
        #pragma unroll
        for (int kh = 0; kh < 2; kh++) {
            uint32_t afr[2][4], bfr[8][2];
            #pragma unroll
            for (int mt = 0; mt < 2; mt++)
                ldsm_x4(afr[mt][0], afr[mt][1], afr[mt][2], afr[mt][3],
                        aBase[buf] + aOff + (uint32_t)(mt * 1280 + kh * 32));
            #pragma unroll
            for (int np = 0; np < 4; np++)
                ldsm_x4(bfr[2 * np][0], bfr[2 * np][1], bfr[2 * np + 1][0], bfr[2 * np + 1][1],
                        bBase[buf] + bOff + (uint32_t)(np * 1280 + kh * 32));
            #pragma unroll
            for (int mt = 0; mt < 2; mt++)
                #pragma unroll
                for (int nt = 0; nt < 8; nt++)
                    mma_f16(acc[mt][nt], afr[mt], bfr[nt]);
        }
        __syncthreads();
        buf ^= 1;
    }

    #pragma unroll
    for (int mt = 0; mt < 2; mt++) {
        int r0 = rowBase + wm0 + mt * 16 + g;
        int r1 = r0 + 8;
        float g0 = (r0 < M) ? gates[r0 * 4 + e] : 0.f;
        float g1 = (r1 < M) ? gates[r1 * 4 + e] : 0.f;
        #pragma unroll
        for (int nt = 0; nt < 8; nt++) {
            int c0 = colBase + wn0 + nt * 8 + 2 * t4;
            float b0v = bias[c0], b1v = bias[c0 + 1];
            if (r0 < M) {
                __half2* p = (__half2*)(hid + (size_t)r0 * KTOT + (size_t)e * H_ + c0);
                *p = __floats2half2_rn(gelu_f(acc[mt][nt][0] + b0v) * g0,
                                       gelu_f(acc[mt][nt][1] + b1v) * g0);
            }
            if (r1 < M) {
                __half2* p = (__half2*)(hid + (size_t)r1 * KTOT + (size_t)e * H_ + c0);
                *p = __floats2half2_rn(gelu_f(acc[mt][nt][2] + b0v) * g1,
                                       gelu_f(acc[mt][nt][3] + b1v) * g1);
            }
        }
    }
}

// ================= expert layer-2: fp16 m16n8k16 split-K GEMM, BK=32 =================
__global__ void __launch_bounds__(256) gemm_f16_l2(
    const __half* __restrict__ A,    // NROW x 8192 (g_hid)
    const __half* __restrict__ W,    // 96 x 8192 (g_w2p)
    const float* __restrict__ eb2,   // (4,96)
    const float* __restrict__ gates, // (NROW,4)
    float* __restrict__ Out,         // (B,96,C)
    int M)
{
    constexpr int NSPLIT = 8, KC = KTOT / NSPLIT;   // 1024
    constexpr int NK = KC / 32;                      // 32
    __shared__ __align__(16) __half As[2][128][40];
    __shared__ __align__(16) __half Ws[2][96][40];

    int tid = threadIdx.x;
    int rowBase = blockIdx.y * 128;
    int kBase = blockIdx.z * KC;
    int lane = tid & 31, warp = tid >> 5;
    int g = lane >> 2, t4 = lane & 3;
    int wm0 = (warp >> 1) * 32, wn0 = (warp & 1) * 48;

    uint32_t aBase[2] = { smem_u32(&As[0][0][0]), smem_u32(&As[1][0][0]) };
    uint32_t bBase[2] = { smem_u32(&Ws[0][0][0]), smem_u32(&Ws[1][0][0]) };
    uint32_t aOff = (uint32_t)(((wm0 + (lane & 15)) * 40 + ((lane >> 4) << 3)) * 2);
    uint32_t bOff = (uint32_t)(((wn0 + (lane & 7) + ((lane >> 4) << 3)) * 40
                               + (((lane >> 3) & 1) << 3)) * 2);

    float acc[2][6][4];
    #pragma unroll
    for (int i = 0; i < 2; i++)
        #pragma unroll
        for (int j = 0; j < 6; j++)
            #pragma unroll
            for (int q = 0; q < 4; q++) acc[i][j][q] = 0.f;

    auto load_tile = [&](int it, int buf) {
        int k0 = kBase + it * 32;
        #pragma unroll
        for (int j = 0; j < 2; j++) {
            int i = tid + 256 * j;
            int r = i >> 2, c = i & 3;
            int gm = rowBase + r;
            int gmc = gm < M ? gm : (M - 1);
            cp_async16g(&As[buf][r][c * 8],
                        A + (size_t)gmc * KTOT + k0 + c * 8,
                        gm < M ? 16 : 0);
        }
        for (int i = tid; i < 96 * 4; i += 256) {
            int r = i >> 2, c = i & 3;
            cp_async16g(&Ws[buf][r][c * 8],
                        W + (size_t)r * KTOT + k0 + c * 8, 16);
        }
    };

    int buf = 0;
    load_tile(0, 0); cp_commit();
    for (int it = 0; it < NK; it++) {
        if (it + 1 < NK) { load_tile(it + 1, buf ^ 1); cp_commit(); cp_wait<1>(); }
        else             { cp_wait<0>(); }
        __syncthreads();
        #pragma unroll
        for (int kh = 0; kh < 2; kh++) {
            uint32_t afr[2][4], bfr[6][2];
            #pragma unroll
            for (int mt = 0; mt < 2; mt++)
                ldsm_x4(afr[mt][0], afr[mt][1], afr[mt][2], afr[mt][3],
                        aBase[buf] + aOff + (uint32_t)(mt * 1280 + kh * 32));
            #pragma unroll
            for (int np = 0; np < 3; np++)
                ldsm_x4(bfr[2 * np][0], bfr[2 * np][1], bfr[2 * np + 1][0], bfr[2 * np + 1][1],
                        bBase[buf] + bOff + (uint32_t)(np * 1280 + kh * 32));
            #pragma unroll
            for (int mt = 0; mt < 2; mt++)
                #pragma unroll
                for (int nt = 0; nt < 6; nt++)
                    mma_f16(acc[mt][nt], afr[mt], bfr[nt]);
        }
        __syncthreads();
        buf ^= 1;
    }

    #pragma unroll
    for (int mt = 0; mt < 2; mt++) {
        int rr[2] = { rowBase + wm0 + mt * 16 + g, rowBase + wm0 + mt * 16 + g + 8 };
        #pragma unroll
        for (int hh = 0; hh < 2; hh++) {
            int gm = rr[hh];
            if (gm >= M) continue;
            int bb = gm / C_, cc = gm % C_;
            #pragma unroll
            for (int nt = 0; nt < 6; nt++) {
                int c0 = wn0 + nt * 8 + 2 * t4;
                #pragma unroll
                for (int q = 0; q < 2; q++) {
                    int gn = c0 + q;
                    float v = acc[mt][nt][hh * 2 + q];
                    if (blockIdx.z == 0) {
                        float bsum = 0.f;
                        #pragma unroll
                        for (int ee = 0; ee < E_; ee++)
                            bsum += gates[gm * 4 + ee] * eb2[ee * P_ + gn];
                        v += bsum;
                    }
                    atomicAdd(&Out[((size_t)bb * P_ + gn) * C_ + cc], v);
                }
            }
        }
    }
}

// ---------------- bn + transpose: x (B,L,C) -> h (B,C,L) with mdm_bn ----------------
__global__ void bn_transpose_kernel(const float* __restrict__ x,
                                    const float* __restrict__ w,
                                    const float* __restrict__ b,
                                    float* __restrict__ h)
{
    __shared__ float tile[32][33];
    int bi = blockIdx.z;
    int l0 = blockIdx.x * 32;
    int c0 = blockIdx.y * 32;
    int tx = threadIdx.x, ty = threadIdx.y;   // 32 x 8
    #pragma unroll
    for (int i = 0; i < 32; i += 8) {
        int l = l0 + ty + i, c = c0 + tx;
        tile[ty + i][tx] = (l < L_ && c < C_) ? x[((size_t)bi * L_ + l) * C_ + c] : 0.f;
    }
    __syncthreads();
    #pragma unroll
    for (int i = 0; i < 32; i += 8) {
        int c = c0 + ty + i, l = l0 + tx;
        if (c < C_ && l < L_) {
            float v = tile[tx][ty + i];
            int wi = c * L_ + l;
            h[((size_t)bi * C_ + c) * L_ + l] = v * (w[wi] * INV_) + b[wi];
        }
    }
}

// ---------------- avg-pool by 2 along last dim ----------------
__global__ void pool2_kernel(const float* __restrict__ in, float* __restrict__ out, int Lout)
{
    int idx = blockIdx.x * blockDim.x + threadIdx.x;
    int total = NROW * Lout;
    if (idx >= total) return;
    int r = idx / Lout, j = idx % Lout;
    const float* p = in + (size_t)r * 2 * Lout + 2 * j;
    out[idx] = 0.5f * (p[0] + p[1]);
}

// ---------------- mixer fp32 GEMM, BM=32 for occupancy ----------------
template<int ACT, int BM, int TM>
__global__ void __launch_bounds__(256) gemm_a(
    const float* __restrict__ A, int lda,
    const float* __restrict__ W,
    const float* __restrict__ bias,
    const float* __restrict__ resid,
    float* __restrict__ Cout, int ldc,
    int M, int N, int K)
{
    constexpr int BN = 128, BK = 16, TN = 8;
    __shared__ __align__(16) float As[BK][BM + 4];
    __shared__ __align__(16) float Ws[BK][BN + 4];
    int tid = threadIdx.x;
    int ty = tid >> 4, tx = tid & 15;
    int rowBase = blockIdx.y * BM, colBase = blockIdx.x * BN;
    float acc[TM][TN] = {};

    for (int k0 = 0; k0 < K; k0 += BK) {
        for (int i = tid; i < BM * BK; i += 256) {
            int m = i / BK, kk = i % BK;
            int gk = k0 + kk;
            int gm = rowBase + m;
            As[kk][m] = (gm < M && gk < K) ? A[(size_t)gm * lda + gk] : 0.f;
        }
        for (int i = tid; i < BN * BK; i += 256) {
            int m = i / BK, kk = i % BK;
            int gk = k0 + kk;
            int gn = colBase + m;
            Ws[kk][m] = (gn < N && gk < K) ? W[(size_t)gn * K + gk] : 0.f;
        }
        __syncthreads();
        #pragma unroll
        for (int kk = 0; kk < BK; kk++) {
            float a[TM], bf[TN];
            #pragma unroll
            for (int i = 0; i < TM; i++) a[i] = As[kk][ty * TM + i];
            *(float4*)&bf[0] = *(const float4*)&Ws[kk][tx * TN];
            *(float4*)&bf[4] = *(const float4*)&Ws[kk][tx * TN + 4];
            #pragma unroll
            for (int i = 0; i < TM; i++)
                #pragma unroll
                for (int j = 0; j < TN; j++)
                    acc[i][j] += a[i] * bf[j];
        }
        __syncthreads();
    }

    #pragma unroll
    for (int i = 0; i < TM; i++) {
        int gm = rowBase + ty * TM + i;
        if (gm >= M) continue;
        #pragma unroll
        for (int j = 0; j < TN; j++) {
            int gn = colBase + tx * TN + j;
            if (gn >= N) continue;
            float v = acc[i][j] + (bias ? bias[gn] : 0.f);
            if (ACT == 1) v = gelu_f(v);
            if (resid) v += resid[(size_t)gm * N + gn];
            Cout[(size_t)gm * ldc + gn] = v;
        }
    }
}

// ---------------- gating ----------------
__global__ void gate_kernel(const float* __restrict__ te,
                            const float* __restrict__ gw,
                            const float* __restrict__ gb,
                            float* __restrict__ gates)
{
    int warp = (blockIdx.x * blockDim.x + threadIdx.x) >> 5;
    int lane = threadIdx.x & 31;
    if (warp >= NROW) return;
    const float* row = te + (size_t)warp * L_;
    float acc[E_] = {0.f, 0.f, 0.f, 0.f};
    for (int l = lane; l < L_; l += 32) {
        float xv = row[l];
        #pragma unroll
        for (int e = 0; e < E_; e++) acc[e] += xv * gw[e * L_ + l];
    }
    #pragma unroll
    for (int off = 16; off; off >>= 1)
        #pragma unroll
        for (int e = 0; e < E_; e++)
            acc[e] += __shfl_xor_sync(0xffffffffu, acc[e], off);
    if (lane == 0) {
        float lg[E_], arr[E_];
        #pragma unroll
        for (int e = 0; e < E_; e++) { lg[e] = acc[e] + gb[e]; arr[e] = lg[e]; }
        #pragma unroll
        for (int i = 0; i < 3; i++)
            #pragma unroll
            for (int j = 0; j < 3; j++)
                if (arr[j] > arr[j + 1]) { float tmp = arr[j]; arr[j] = arr[j + 1]; arr[j + 1] = tmp; }
        float kth = arr[E_ - 2];
        float mx = lg[0];
        #pragma unroll
        for (int e = 1; e < E_; e++) mx = fmaxf(mx, lg[e]);
        float s[E_], ssum = 0.f;
        #pragma unroll
        for (int e = 0; e < E_; e++) { s[e] = expf(lg[e] - mx); ssum += s[e]; }
        #pragma unroll
        for (int e = 0; e < E_; e++) s[e] /= ssum;
        float dec[E_];
        #pragma unroll
        for (int e = 0; e < E_; e++)
            dec[e] = (lg[e] < kth) ? 10.f * logf(s[e] + 1.f) : 10.f * (expf(s[e]) - 1.f);
        float m2 = dec[0];
        #pragma unroll
        for (int e = 1; e < E_; e++) m2 = fmaxf(m2, dec[e]);
        float t2[E_], su = 0.f;
        #pragma unroll
        for (int e = 0; e < E_; e++) { t2[e] = expf(dec[e] - m2); su += t2[e]; }
        #pragma unroll
        for (int e = 0; e < E_; e++) gates[(size_t)warp * E_ + e] = t2[e] / su;
    }
}

// ---------------- ddi bn ----------------
__global__ void bn_ddi_kernel(const float* __restrict__ te,
                              const float* __restrict__ w,
                              const float* __restrict__ b,
                              float* __restrict__ out)
{
    int idx = blockIdx.x * blockDim.x + threadIdx.x;
    if (idx >= NROW * L_) return;
    int l = idx % L_;
    int c = (idx / L_) % C_;
    int wi = c * L_ + l;
    out[idx] = te[idx] * (w[wi] * INV_) + b[wi];
}

// ---------------- ddi sequential scan (writes fp16 output) ----------------
__global__ void ddi_scan_kernel(const float* __restrict__ d,
                                const float* __restrict__ n1w,
                                const float* __restrict__ n1b,
                                const float* __restrict__ agg_w,
                                const float* __restrict__ agg_b,
                                __half* __restrict__ out)
{
    __shared__ float aw[PATCH * PATCH];
    __shared__ float ab[PATCH];
    for (int i = threadIdx.x; i < PATCH * PATCH; i += blockDim.x) aw[i] = agg_w[i];
    for (int i = threadIdx.x; i < PATCH; i += blockDim.x) ab[i] = agg_b[i];
    __syncthreads();
    int row = blockIdx.x * blockDim.x + threadIdx.x;
    if (row >= NROW) return;
    int c = row % C_;
    float w[PATCH], bb[PATCH], prev[PATCH];
    #pragma unroll
    for (int p = 0; p < PATCH; p++) {
        w[p]  = n1w[c * PATCH + p] * INV_;
        bb[p] = n1b[c * PATCH + p];
    }
    const float* drow = d + (size_t)row * L_;
    __half* orow = out + (size_t)row * L_;
    #pragma unroll
    for (int p = 0; p < PATCH; p++) {
        prev[p] = drow[p];
        orow[p] = __float2half_rn(prev[p]);
    }
    for (int t = 1; t < L_ / PATCH; t++) {
        float inp[PATCH], tmp[PATCH];
        #pragma unroll
        for (int p = 0; p < PATCH; p++) inp[p] = prev[p] * w[p] + bb[p];
        #pragma unroll
        for (int m = 0; m < PATCH; m++) {
            float s = ab[m];
            #pragma unroll
            for (int p = 0; p < PATCH; p++) s += inp[p] * aw[m * PATCH + p];
            tmp[m] = gelu_f(s);
        }
        #pragma unroll
        for (int p = 0; p < PATCH; p++) {
            prev[p] = tmp[p] + drow[t * PATCH + p];
            orow[t * PATCH + p] = __float2half_rn(prev[p]);
        }
    }
}

// ---------------- repack ew2 (E,P,H) -> (P, E*H), fp16 ----------------
__global__ void repack_w2_kernel(const float* __restrict__ ew2, __half* __restrict__ w2p)
{
    int idx = blockIdx.x * blockDim.x + threadIdx.x;
    if (idx >= P_ * KTOT) return;
    int p = idx / KTOT;
    int r = idx % KTOT;
    int e = r / H_, hh = r % H_;
    w2p[idx] = __float2half_rn(ew2[((size_t)e * P_ + p) * H_ + hh]);
}

__global__ void zero_kernel(float* o, int n)
{
    int idx = blockIdx.x * blockDim.x + threadIdx.x;
    if (idx < n) o[idx] = 0.f;
}

// ---------------- launch ----------------
extern "C" void kernel_launch(void* const* d_in, const int* in_sizes, int n_in,
                              void* d_out, int out_size)
{
    // Map inputs, skipping the scalar 'k' (size 1) wherever it sits.
    const float* in[27];
    int pi = 0;
    for (int i = 0; i < n_in && pi < 27; i++) {
        if (in_sizes[i] == 1) continue;
        in[pi++] = (const float*)d_in[i];
    }
    const float* x    = in[0];
    const float* mdw  = in[1];  const float* mdb  = in[2];
    const float* w1s[3] = { in[3], in[7],  in[11] };
    const float* b1s[3] = { in[4], in[8],  in[12] };
    const float* w2s[3] = { in[5], in[9],  in[13] };
    const float* b2s[3] = { in[6], in[10], in[14] };
    const float* ddw  = in[15]; const float* ddb  = in[16];
    const float* n1w  = in[17]; const float* n1b  = in[18];
    const float* aggw = in[19]; const float* aggb = in[20];
    const float* gw   = in[21]; const float* gb   = in[22];
    const float* ew1  = in[23]; const float* eb1  = in[24];
    const float* ew2  = in[25]; const float* eb2  = in[26];

    float *h, *s2, *s4, *s8, *t, *cur, *te, *dd, *gates;
    __half *ddih, *w1h, *hid, *w2p;
    cudaGetSymbolAddress((void**)&h,    g_h);
    cudaGetSymbolAddress((void**)&s2,   g_s2);
    cudaGetSymbolAddress((void**)&s4,   g_s4);
    cudaGetSymbolAddress((void**)&s8,   g_s8);
    cudaGetSymbolAddress((void**)&t,    g_t);
    cudaGetSymbolAddress((void**)&cur,  g_cur);
    cudaGetSymbolAddress((void**)&te,   g_te);
    cudaGetSymbolAddress((void**)&dd,   g_d);
    cudaGetSymbolAddress((void**)&ddih, g_ddih);
    cudaGetSymbolAddress((void**)&w1h,  g_w1h);
    cudaGetSymbolAddress((void**)&gates,g_gates);
    cudaGetSymbolAddress((void**)&hid,  g_hid);
    cudaGetSymbolAddress((void**)&w2p,  g_w2p);

    float* out = (float*)d_out;

    // 1) bn + transpose -> h (B,C,L)
    {
        dim3 tb(32, 8);
        dim3 tg((L_ + 31) / 32, (C_ + 31) / 32, B_);
        bn_transpose_kernel<<<tg, tb>>>(x, mdw, mdb, h);
    }
    // 2) pools
    pool2_kernel<<<(NROW * 168 + 255) / 256, 256>>>(h,  s2, 168);
    pool2_kernel<<<(NROW * 84  + 255) / 256, 256>>>(s2, s4, 84);
    pool2_kernel<<<(NROW * 42  + 255) / 256, 256>>>(s4, s8, 42);

    // 3) mixer stages (fp32, BM=32 for occupancy)
    auto mgrid = [](int M, int N) { return dim3((N + 127) / 128, (M + 31) / 32); };
    gemm_a<1,32,2><<<mgrid(NROW, 42), 256>>>(s8, 42, w1s[0], b1s[0], nullptr, t,   42,  NROW, 42,  42);
    gemm_a<0,32,2><<<mgrid(NROW, 84), 256>>>(t,  42, w2s[0], b2s[0], s4,      cur, 84,  NROW, 84,  42);
    gemm_a<1,32,2><<<mgrid(NROW, 84), 256>>>(cur,84, w1s[1], b1s[1], nullptr, t,   84,  NROW, 84,  84);
    gemm_a<0,32,2><<<mgrid(NROW,168), 256>>>(t,  84, w2s[1], b2s[1], s2,      cur, 168, NROW, 168, 84);
    gemm_a<1,32,2><<<mgrid(NROW,168), 256>>>(cur,168,w1s[2], b1s[2], nullptr, t,   168, NROW, 168, 168);
    gemm_a<0,32,2><<<mgrid(NROW,336), 256>>>(t,  168,w2s[2], b2s[2], h,       te,  336, NROW, 336, 168);

    // 4) gating from te
    gate_kernel<<<(NROW * 32 + 255) / 256, 256>>>(te, gw, gb, gates);

    // 5) ddi: bn then 27-step scan (scan emits fp16 ddi directly)
    bn_ddi_kernel<<<(NROW * L_ + 255) / 256, 256>>>(te, ddw, ddb, dd);
    ddi_scan_kernel<<<(NROW + 127) / 128, 128>>>(dd, n1w, n1b, aggw, aggb, ddih);

    // 6) convert expert weights to fp16
    f2h_kernel<<<(E_ * H_ * L_ + 255) / 256, 256>>>(ew1, w1h, E_ * H_ * L_);
    repack_w2_kernel<<<(P_ * KTOT + 255) / 256, 256>>>(ew2, w2p);
    zero_kernel<<<(out_size + 255) / 256, 256>>>(out, out_size);

    // 7) experts — fp16 m16n8k16 tensor cores, BK=32 pipelines
    {
        dim3 tg(H_ / 128, (NROW + 127) / 128, E_);
        gemm_f16_l1<<<tg, 256>>>(ddih, w1h, eb1, gates, hid, NROW);
    }
    {
        dim3 tg(1, (NROW + 127) / 128, 8);
        gemm_f16_l2<<<tg, 256>>>(hid, w2p, eb2, gates, out, NROW);
    }
}

// round 11
// speedup vs baseline: 1.4485x; 1.1820x over previous
#include <cuda_runtime.h>
#include <cuda_fp16.h>
#include <cstdint>

// ---------------- problem constants ----------------
#define B_    32
#define L_    336
#define C_    321
#define P_    96
#define E_    4
#define H_    2048
#define PATCH 12
#define NROW  (B_*C_)          // 10272
#define KTOT  (E_*H_)          // 8192
#define INV_  0.99999499987499937f   // 1/sqrt(1+1e-5)

// ---------------- scratch (static device globals; no allocation) ----------------
__device__ float  g_h  [NROW*L_];
__device__ float  g_s2 [NROW*168];
__device__ float  g_s4 [NROW*84];
__device__ float  g_s8 [NROW*42];
__device__ float  g_t  [NROW*168];
__device__ float  g_cur[NROW*L_];
__device__ float  g_te [NROW*L_];
__device__ float  g_d  [NROW*L_];
__device__ __half g_ddih[NROW*L_];             // fp16 ddi (scan writes half)
__device__ __half g_w1h[E_*H_*L_];             // fp16 ew1 (5.5 MB)
__device__ float  g_gates[NROW*E_];
__device__ __half g_hid[(size_t)NROW*KTOT];    // 168 MB fp16
__device__ __half g_w2p[P_*KTOT];              // repacked fp16 ew2

__device__ __forceinline__ float gelu_f(float x) {
    return 0.5f * x * (1.0f + erff(x * 0.70710678118654752f));
}

// ---------------- fp16 mma helpers ----------------
__device__ __forceinline__ void mma_f16(float* c, const uint32_t* a, const uint32_t* b) {
    asm volatile(
        "mma.sync.aligned.m16n8k16.row.col.f32.f16.f16.f32 "
        "{%0,%1,%2,%3}, {%4,%5,%6,%7}, {%8,%9}, {%0,%1,%2,%3};"
        : "+f"(c[0]), "+f"(c[1]), "+f"(c[2]), "+f"(c[3])
        : "r"(a[0]), "r"(a[1]), "r"(a[2]), "r"(a[3]), "r"(b[0]), "r"(b[1]));
}
__device__ __forceinline__ void ldsm_x4(uint32_t& r0, uint32_t& r1, uint32_t& r2, uint32_t& r3,
                                        uint32_t saddr) {
    asm volatile("ldmatrix.sync.aligned.m8n8.x4.shared.b16 {%0,%1,%2,%3}, [%4];"
                 : "=r"(r0), "=r"(r1), "=r"(r2), "=r"(r3) : "r"(saddr));
}
__device__ __forceinline__ uint32_t smem_u32(const void* p) {
    return (uint32_t)__cvta_generic_to_shared(p);
}
__device__ __forceinline__ void cp_async16(void* smem, const void* gmem, int bytes) {
    uint32_t saddr = smem_u32(smem);
    asm volatile("cp.async.ca.shared.global [%0], [%1], 16, %2;"
                 :: "r"(saddr), "l"(gmem), "r"(bytes));
}
__device__ __forceinline__ void cp_commit() { asm volatile("cp.async.commit_group;"); }
template<int N> __device__ __forceinline__ void cp_wait() {
    asm volatile("cp.async.wait_group %0;" :: "n"(N));
}

// ---------------- fp32 -> fp16 convert (elementwise) ----------------
__global__ void f2h_kernel(const float* __restrict__ in, __half* __restrict__ out, int n)
{
    int idx = blockIdx.x * blockDim.x + threadIdx.x;
    if (idx < n) out[idx] = __float2half_rn(in[idx]);
}

// ================= expert layer-1: fp16 m16n8k16 GEMM (R8 config: BK=16) =================
__global__ void __launch_bounds__(256) gemm_f16_l1(
    const __half* __restrict__ A,     // NROW x 336
    const __half* __restrict__ W1,    // (E, 2048, 336)
    const float* __restrict__ eb1,    // (E, 2048)
    const float* __restrict__ gates,  // (NROW, 4)
    __half* __restrict__ hid,         // NROW x 8192
    int M)
{
    constexpr int KK = L_;            // 336
    constexpr int NK = KK / 16;       // 21
    __shared__ __align__(16) __half As[2][128][24];
    __shared__ __align__(16) __half Ws[2][128][24];

    int tid = threadIdx.x;
    int e   = blockIdx.z;
    const __half* W   = W1 + (size_t)e * H_ * KK;
    const float* bias = eb1 + (size_t)e * H_;
    int rowBase = blockIdx.y * 128;
    int colBase = blockIdx.x * 128;
    int lane = tid & 31, warp = tid >> 5;
    int g = lane >> 2, t4 = lane & 3;
    int wm0 = (warp >> 1) * 32, wn0 = (warp & 1) * 64;

    uint32_t aBase[2] = { smem_u32(&As[0][0][0]), smem_u32(&As[1][0][0]) };
    uint32_t bBase[2] = { smem_u32(&Ws[0][0][0]), smem_u32(&Ws[1][0][0]) };
    uint32_t aOff = (uint32_t)(((wm0 + (lane & 15)) * 24 + ((lane >> 4) << 3)) * 2);
    uint32_t bOff = (uint32_t)(((wn0 + (lane & 7) + ((lane >> 4) << 3)) * 24
                               + (((lane >> 3) & 1) << 3)) * 2);

    float acc[2][8][4];
    #pragma unroll
    for (int i = 0; i < 2; i++)
        #pragma unroll
        for (int j = 0; j < 8; j++)
            #pragma unroll
            for (int q = 0; q < 4; q++) acc[i][j][q] = 0.f;

    auto load_tile = [&](int it, int buf) {
        int k0 = it * 16;
        int r = tid >> 1, j = tid & 1;       // 128 rows x 2 chunks of 8 halves
        int gm = rowBase + r;
        int gmc = gm < M ? gm : (M - 1);
        cp_async16(&As[buf][r][j * 8],
                   A + (size_t)gmc * KK + k0 + j * 8,
                   gm < M ? 16 : 0);
        cp_async16(&Ws[buf][r][j * 8],
                   W + (size_t)(colBase + r) * KK + k0 + j * 8, 16);
    };

    int buf = 0;
    load_tile(0, 0); cp_commit();
    for (int it = 0; it < NK; it++) {
        if (it + 1 < NK) { load_tile(it + 1, buf ^ 1); cp_commit(); cp_wait<1>(); }
        else             { cp_wait<0>(); }
        __syncthreads();
        {
            uint32_t afr[2][4], bfr[8][2];
            #pragma unroll
            for (int mt = 0; mt < 2; mt++)
                ldsm_x4(afr[mt][0], afr[mt][1], afr[mt][2], afr[mt][3],
                        aBase[buf] + aOff + (uint32_t)(mt * 768));
            #pragma unroll
            for (int np = 0; np < 4; np++)
                ldsm_x4(bfr[2 * np][0], bfr[2 * np][1], bfr[2 * np + 1][0], bfr[2 * np + 1][1],
                        bBase[buf] + bOff + (uint32_t)(np * 768));
            #pragma unroll
            for (int mt = 0; mt < 2; mt++)
                #pragma unroll
                for (int nt = 0; nt < 8; nt++)
                    mma_f16(acc[mt][nt], afr[mt], bfr[nt]);
        }
        __syncthreads();
        buf ^= 1;
    }

    #pragma unroll
    for (int mt = 0; mt < 2; mt++) {
        int r0 = rowBase + wm0 + mt * 16 + g;
        int r1 = r0 + 8;
        float g0 = (r0 < M) ? gates[r0 * 4 + e] : 0.f;
        float g1 = (r1 < M) ? gates[r1 * 4 + e] : 0.f;
        #pragma unroll
        for (int nt = 0; nt < 8; nt++) {
            int c0 = colBase + wn0 + nt * 8 + 2 * t4;
            float b0v = bias[c0], b1v = bias[c0 + 1];
            if (r0 < M) {
                __half2* p = (__half2*)(hid + (size_t)r0 * KTOT + (size_t)e * H_ + c0);
                *p = __floats2half2_rn(gelu_f(acc[mt][nt][0] + b0v) * g0,
                                       gelu_f(acc[mt][nt][1] + b1v) * g0);
            }
            if (r1 < M) {
                __half2* p = (__half2*)(hid + (size_t)r1 * KTOT + (size_t)e * H_ + c0);
                *p = __floats2half2_rn(gelu_f(acc[mt][nt][2] + b0v) * g1,
                                       gelu_f(acc[mt][nt][3] + b1v) * g1);
            }
        }
    }
}

// ================= expert layer-2: fp16 m16n8k16 split-K GEMM (R8 config) =================
__global__ void __launch_bounds__(256) gemm_f16_l2(
    const __half* __restrict__ A,    // NROW x 8192 (g_hid)
    const __half* __restrict__ W,    // 96 x 8192 (g_w2p)
    const float* __restrict__ eb2,   // (4,96)
    const float* __restrict__ gates, // (NROW,4)
    float* __restrict__ Out,         // (B,96,C)
    int M)
{
    constexpr int NSPLIT = 8, KC = KTOT / NSPLIT;   // 1024
    constexpr int NK = KC / 16;                      // 64
    __shared__ __align__(16) __half As[2][128][24];
    __shared__ __align__(16) __half Ws[2][96][24];

    int tid = threadIdx.x;
    int rowBase = blockIdx.y * 128;
    int kBase = blockIdx.z * KC;
    int lane = tid & 31, warp = tid >> 5;
    int g = lane >> 2, t4 = lane & 3;
    int wm0 = (warp >> 1) * 32, wn0 = (warp & 1) * 48;

    uint32_t aBase[2] = { smem_u32(&As[0][0][0]), smem_u32(&As[1][0][0]) };
    uint32_t bBase[2] = { smem_u32(&Ws[0][0][0]), smem_u32(&Ws[1][0][0]) };
    uint32_t aOff = (uint32_t)(((wm0 + (lane & 15)) * 24 + ((lane >> 4) << 3)) * 2);
    uint32_t bOff = (uint32_t)(((wn0 + (lane & 7) + ((lane >> 4) << 3)) * 24
                               + (((lane >> 3) & 1) << 3)) * 2);

    float acc[2][6][4];
    #pragma unroll
    for (int i = 0; i < 2; i++)
        #pragma unroll
        for (int j = 0; j < 6; j++)
            #pragma unroll
            for (int q = 0; q < 4; q++) acc[i][j][q] = 0.f;

    auto load_tile = [&](int it, int buf) {
        int k0 = kBase + it * 16;
        int r = tid >> 1, j = tid & 1;
        int gm = rowBase + r;
        int gmc = gm < M ? gm : (M - 1);
        cp_async16(&As[buf][r][j * 8],
                   A + (size_t)gmc * KTOT + k0 + j * 8,
                   gm < M ? 16 : 0);
        if (r < 96)
            cp_async16(&Ws[buf][r][j * 8],
                       W + (size_t)r * KTOT + k0 + j * 8, 16);
    };

    int buf = 0;
    load_tile(0, 0); cp_commit();
    for (int it = 0; it < NK; it++) {
        if (it + 1 < NK) { load_tile(it + 1, buf ^ 1); cp_commit(); cp_wait<1>(); }
        else             { cp_wait<0>(); }
        __syncthreads();
        {
            uint32_t afr[2][4], bfr[6][2];
            #pragma unroll
            for (int mt = 0; mt < 2; mt++)
                ldsm_x4(afr[mt][0], afr[mt][1], afr[mt][2], afr[mt][3],
                        aBase[buf] + aOff + (uint32_t)(mt * 768));
            #pragma unroll
            for (int np = 0; np < 3; np++)
                ldsm_x4(bfr[2 * np][0], bfr[2 * np][1], bfr[2 * np + 1][0], bfr[2 * np + 1][1],
                        bBase[buf] + bOff + (uint32_t)(np * 768));
            #pragma unroll
            for (int mt = 0; mt < 2; mt++)
                #pragma unroll
                for (int nt = 0; nt < 6; nt++)
                    mma_f16(acc[mt][nt], afr[mt], bfr[nt]);
        }
        __syncthreads();
        buf ^= 1;
    }

    #pragma unroll
    for (int mt = 0; mt < 2; mt++) {
        int rr[2] = { rowBase + wm0 + mt * 16 + g, rowBase + wm0 + mt * 16 + g + 8 };
        #pragma unroll
        for (int hh = 0; hh < 2; hh++) {
            int gm = rr[hh];
            if (gm >= M) continue;
            int bb = gm / C_, cc = gm % C_;
            #pragma unroll
            for (int nt = 0; nt < 6; nt++) {
                int c0 = wn0 + nt * 8 + 2 * t4;
                #pragma unroll
                for (int q = 0; q < 2; q++) {
                    int gn = c0 + q;
                    float v = acc[mt][nt][hh * 2 + q];
                    if (blockIdx.z == 0) {
                        float bsum = 0.f;
                        #pragma unroll
                        for (int ee = 0; ee < E_; ee++)
                            bsum += gates[gm * 4 + ee] * eb2[ee * P_ + gn];
                        v += bsum;
                    }
                    atomicAdd(&Out[((size_t)bb * P_ + gn) * C_ + cc], v);
                }
            }
        }
    }
}

// ---------------- bn + transpose: x (B,L,C) -> h (B,C,L) with mdm_bn ----------------
__global__ void bn_transpose_kernel(const float* __restrict__ x,
                                    const float* __restrict__ w,
                                    const float* __restrict__ b,
                                    float* __restrict__ h)
{
    __shared__ float tile[32][33];
    int bi = blockIdx.z;
    int l0 = blockIdx.x * 32;
    int c0 = blockIdx.y * 32;
    int tx = threadIdx.x, ty = threadIdx.y;   // 32 x 8
    #pragma unroll
    for (int i = 0; i < 32; i += 8) {
        int l = l0 + ty + i, c = c0 + tx;
        tile[ty + i][tx] = (l < L_ && c < C_) ? x[((size_t)bi * L_ + l) * C_ + c] : 0.f;
    }
    __syncthreads();
    #pragma unroll
    for (int i = 0; i < 32; i += 8) {
        int c = c0 + ty + i, l = l0 + tx;
        if (c < C_ && l < L_) {
            float v = tile[tx][ty + i];
            int wi = c * L_ + l;
            h[((size_t)bi * C_ + c) * L_ + l] = v * (w[wi] * INV_) + b[wi];
        }
    }
}

// ---------------- avg-pool by 2 along last dim ----------------
__global__ void pool2_kernel(const float* __restrict__ in, float* __restrict__ out, int Lout)
{
    int idx = blockIdx.x * blockDim.x + threadIdx.x;
    int total = NROW * Lout;
    if (idx >= total) return;
    int r = idx / Lout, j = idx % Lout;
    const float* p = in + (size_t)r * 2 * Lout + 2 * j;
    out[idx] = 0.5f * (p[0] + p[1]);
}

// ---------------- mixer fp32 GEMM, BM=64 x BN=64 tiles ----------------
template<int ACT>
__global__ void __launch_bounds__(256) gemm_m(
    const float* __restrict__ A, int lda,
    const float* __restrict__ W,
    const float* __restrict__ bias,
    const float* __restrict__ resid,
    float* __restrict__ Cout, int ldc,
    int M, int N, int K)
{
    constexpr int BM = 64, BN = 64, BK = 16, TM = 4, TN = 4;
    __shared__ __align__(16) float As[BK][BM + 4];
    __shared__ __align__(16) float Ws[BK][BN + 4];
    int tid = threadIdx.x;
    int ty = tid >> 4, tx = tid & 15;          // 16 x 16 threads
    int rowBase = blockIdx.y * BM, colBase = blockIdx.x * BN;
    float acc[TM][TN] = {};

    for (int k0 = 0; k0 < K; k0 += BK) {
        #pragma unroll
        for (int i = 0; i < 4; i++) {
            int idx = tid + 256 * i;          // 0..1023
            int m = idx >> 4, kk = idx & 15;
            int gk = k0 + kk;
            int gm = rowBase + m;
            As[kk][m] = (gm < M && gk < K) ? A[(size_t)gm * lda + gk] : 0.f;
            int gn = colBase + m;
            Ws[kk][m] = (gn < N && gk < K) ? W[(size_t)gn * K + gk] : 0.f;
        }
        __syncthreads();
        #pragma unroll
        for (int kk = 0; kk < BK; kk++) {
            float a[TM], bf[TN];
            *(float4*)&a[0]  = *(const float4*)&As[kk][ty * TM];
            *(float4*)&bf[0] = *(const float4*)&Ws[kk][tx * TN];
            #pragma unroll
            for (int i = 0; i < TM; i++)
                #pragma unroll
                for (int j = 0; j < TN; j++)
                    acc[i][j] += a[i] * bf[j];
        }
        __syncthreads();
    }

    #pragma unroll
    for (int i = 0; i < TM; i++) {
        int gm = rowBase + ty * TM + i;
        if (gm >= M) continue;
        #pragma unroll
        for (int j = 0; j < TN; j++) {
            int gn = colBase + tx * TN + j;
            if (gn >= N) continue;
            float v = acc[i][j] + (bias ? bias[gn] : 0.f);
            if (ACT == 1) v = gelu_f(v);
            if (resid) v += resid[(size_t)gm * N + gn];
            Cout[(size_t)gm * ldc + gn] = v;
        }
    }
}

// ---------------- gating ----------------
__global__ void gate_kernel(const float* __restrict__ te,
                            const float* __restrict__ gw,
                            const float* __restrict__ gb,
                            float* __restrict__ gates)
{
    int warp = (blockIdx.x * blockDim.x + threadIdx.x) >> 5;
    int lane = threadIdx.x & 31;
    if (warp >= NROW) return;
    const float* row = te + (size_t)warp * L_;
    float acc[E_] = {0.f, 0.f, 0.f, 0.f};
    for (int l = lane; l < L_; l += 32) {
        float xv = row[l];
        #pragma unroll
        for (int e = 0; e < E_; e++) acc[e] += xv * gw[e * L_ + l];
    }
    #pragma unroll
    for (int off = 16; off; off >>= 1)
        #pragma unroll
        for (int e = 0; e < E_; e++)
            acc[e] += __shfl_xor_sync(0xffffffffu, acc[e], off);
    if (lane == 0) {
        float lg[E_], arr[E_];
        #pragma unroll
        for (int e = 0; e < E_; e++) { lg[e] = acc[e] + gb[e]; arr[e] = lg[e]; }
        #pragma unroll
        for (int i = 0; i < 3; i++)
            #pragma unroll
            for (int j = 0; j < 3; j++)
                if (arr[j] > arr[j + 1]) { float tmp = arr[j]; arr[j] = arr[j + 1]; arr[j + 1] = tmp; }
        float kth = arr[E_ - 2];
        float mx = lg[0];
        #pragma unroll
        for (int e = 1; e < E_; e++) mx = fmaxf(mx, lg[e]);
        float s[E_], ssum = 0.f;
        #pragma unroll
        for (int e = 0; e < E_; e++) { s[e] = expf(lg[e] - mx); ssum += s[e]; }
        #pragma unroll
        for (int e = 0; e < E_; e++) s[e] /= ssum;
        float dec[E_];
        #pragma unroll
        for (int e = 0; e < E_; e++)
            dec[e] = (lg[e] < kth) ? 10.f * logf(s[e] + 1.f) : 10.f * (expf(s[e]) - 1.f);
        float m2 = dec[0];
        #pragma unroll
        for (int e = 1; e < E_; e++) m2 = fmaxf(m2, dec[e]);
        float t2[E_], su = 0.f;
        #pragma unroll
        for (int e = 0; e < E_; e++) { t2[e] = expf(dec[e] - m2); su += t2[e]; }
        #pragma unroll
        for (int e = 0; e < E_; e++) gates[(size_t)warp * E_ + e] = t2[e] / su;
    }
}

// ---------------- ddi bn ----------------
__global__ void bn_ddi_kernel(const float* __restrict__ te,
                              const float* __restrict__ w,
                              const float* __restrict__ b,
                              float* __restrict__ out)
{
    int idx = blockIdx.x * blockDim.x + threadIdx.x;
    if (idx >= NROW * L_) return;
    int l = idx % L_;
    int c = (idx / L_) % C_;
    int wi = c * L_ + l;
    out[idx] = te[idx] * (w[wi] * INV_) + b[wi];
}

// ---------------- ddi sequential scan (writes fp16 output) ----------------
__global__ void ddi_scan_kernel(const float* __restrict__ d,
                                const float* __restrict__ n1w,
                                const float* __restrict__ n1b,
                                const float* __restrict__ agg_w,
                                const float* __restrict__ agg_b,
                                __half* __restrict__ out)
{
    __shared__ float aw[PATCH * PATCH];
    __shared__ float ab[PATCH];
    for (int i = threadIdx.x; i < PATCH * PATCH; i += blockDim.x) aw[i] = agg_w[i];
    for (int i = threadIdx.x; i < PATCH; i += blockDim.x) ab[i] = agg_b[i];
    __syncthreads();
    int row = blockIdx.x * blockDim.x + threadIdx.x;
    if (row >= NROW) return;
    int c = row % C_;
    float w[PATCH], bb[PATCH], prev[PATCH];
    #pragma unroll
    for (int p = 0; p < PATCH; p++) {
        w[p]  = n1w[c * PATCH + p] * INV_;
        bb[p] = n1b[c * PATCH + p];
    }
    const float* drow = d + (size_t)row * L_;
    __half* orow = out + (size_t)row * L_;
    #pragma unroll
    for (int p = 0; p < PATCH; p++) {
        prev[p] = drow[p];
        orow[p] = __float2half_rn(prev[p]);
    }
    for (int t = 1; t < L_ / PATCH; t++) {
        float inp[PATCH], tmp[PATCH];
        #pragma unroll
        for (int p = 0; p < PATCH; p++) inp[p] = prev[p] * w[p] + bb[p];
        #pragma unroll
        for (int m = 0; m < PATCH; m++) {
            float s = ab[m];
            #pragma unroll
            for (int p = 0; p < PATCH; p++) s += inp[p] * aw[m * PATCH + p];
            tmp[m] = gelu_f(s);
        }
        #pragma unroll
        for (int p = 0; p < PATCH; p++) {
            prev[p] = tmp[p] + drow[t * PATCH + p];
            orow[t * PATCH + p] = __float2half_rn(prev[p]);
        }
    }
}

// ---------------- repack ew2 (E,P,H) -> (P, E*H), fp16 ----------------
__global__ void repack_w2_kernel(const float* __restrict__ ew2, __half* __restrict__ w2p)
{
    int idx = blockIdx.x * blockDim.x + threadIdx.x;
    if (idx >= P_ * KTOT) return;
    int p = idx / KTOT;
    int r = idx % KTOT;
    int e = r / H_, hh = r % H_;
    w2p[idx] = __float2half_rn(ew2[((size_t)e * P_ + p) * H_ + hh]);
}

__global__ void zero_kernel(float* o, int n)
{
    int idx = blockIdx.x * blockDim.x + threadIdx.x;
    if (idx < n) o[idx] = 0.f;
}

// ---------------- launch ----------------
extern "C" void kernel_launch(void* const* d_in, const int* in_sizes, int n_in,
                              void* d_out, int out_size)
{
    // Map inputs, skipping the scalar 'k' (size 1) wherever it sits.
    const float* in[27];
    int pi = 0;
    for (int i = 0; i < n_in && pi < 27; i++) {
        if (in_sizes[i] == 1) continue;
        in[pi++] = (const float*)d_in[i];
    }
    const float* x    = in[0];
    const float* mdw  = in[1];  const float* mdb  = in[2];
    const float* w1s[3] = { in[3], in[7],  in[11] };
    const float* b1s[3] = { in[4], in[8],  in[12] };
    const float* w2s[3] = { in[5], in[9],  in[13] };
    const float* b2s[3] = { in[6], in[10], in[14] };
    const float* ddw  = in[15]; const float* ddb  = in[16];
    const float* n1w  = in[17]; const float* n1b  = in[18];
    const float* aggw = in[19]; const float* aggb = in[20];
    const float* gw   = in[21]; const float* gb   = in[22];
    const float* ew1  = in[23]; const float* eb1  = in[24];
    const float* ew2  = in[25]; const float* eb2  = in[26];

    float *h, *s2, *s4, *s8, *t, *cur, *te, *dd, *gates;
    __half *ddih, *w1h, *hid, *w2p;
    cudaGetSymbolAddress((void**)&h,    g_h);
    cudaGetSymbolAddress((void**)&s2,   g_s2);
    cudaGetSymbolAddress((void**)&s4,   g_s4);
    cudaGetSymbolAddress((void**)&s8,   g_s8);
    cudaGetSymbolAddress((void**)&t,    g_t);
    cudaGetSymbolAddress((void**)&cur,  g_cur);
    cudaGetSymbolAddress((void**)&te,   g_te);
    cudaGetSymbolAddress((void**)&dd,   g_d);
    cudaGetSymbolAddress((void**)&ddih, g_ddih);
    cudaGetSymbolAddress((void**)&w1h,  g_w1h);
    cudaGetSymbolAddress((void**)&gates,g_gates);
    cudaGetSymbolAddress((void**)&hid,  g_hid);
    cudaGetSymbolAddress((void**)&w2p,  g_w2p);

    float* out = (float*)d_out;

    // 1) bn + transpose -> h (B,C,L)
    {
        dim3 tb(32, 8);
        dim3 tg((L_ + 31) / 32, (C_ + 31) / 32, B_);
        bn_transpose_kernel<<<tg, tb>>>(x, mdw, mdb, h);
    }
    // 2) pools
    pool2_kernel<<<(NROW * 168 + 255) / 256, 256>>>(h,  s2, 168);
    pool2_kernel<<<(NROW * 84  + 255) / 256, 256>>>(s2, s4, 84);
    pool2_kernel<<<(NROW * 42  + 255) / 256, 256>>>(s4, s8, 42);

    // 3) mixer stages (fp32, 64x64 tiles)
    auto mgrid = [](int M, int N) { return dim3((N + 63) / 64, (M + 63) / 64); };
    gemm_m<1><<<mgrid(NROW, 42), 256>>>(s8, 42, w1s[0], b1s[0], nullptr, t,   42,  NROW, 42,  42);
    gemm_m<0><<<mgrid(NROW, 84), 256>>>(t,  42, w2s[0], b2s[0], s4,      cur, 84,  NROW, 84,  42);
    gemm_m<1><<<mgrid(NROW, 84), 256>>>(cur,84, w1s[1], b1s[1], nullptr, t,   84,  NROW, 84,  84);
    gemm_m<0><<<mgrid(NROW,168), 256>>>(t,  84, w2s[1], b2s[1], s2,      cur, 168, NROW, 168, 84);
    gemm_m<1><<<mgrid(NROW,168), 256>>>(cur,168,w1s[2], b1s[2], nullptr, t,   168, NROW, 168, 168);
    gemm_m<0><<<mgrid(NROW,336), 256>>>(t,  168,w2s[2], b2s[2], h,       te,  336, NROW, 336, 168);

    // 4) gating from te
    gate_kernel<<<(NROW * 32 + 255) / 256, 256>>>(te, gw, gb, gates);

    // 5) ddi: bn then 27-step scan (scan emits fp16 ddi directly)
    bn_ddi_kernel<<<(NROW * L_ + 255) / 256, 256>>>(te, ddw, ddb, dd);
    ddi_scan_kernel<<<(NROW + 127) / 128, 128>>>(dd, n1w, n1b, aggw, aggb, ddih);

    // 6) convert expert weights to fp16
    f2h_kernel<<<(E_ * H_ * L_ + 255) / 256, 256>>>(ew1, w1h, E_ * H_ * L_);
    repack_w2_kernel<<<(P_ * KTOT + 255) / 256, 256>>>(ew2, w2p);
    zero_kernel<<<(out_size + 255) / 256, 256>>>(out, out_size);

    // 7) experts — fp16 m16n8k16 tensor cores (R8 config)
    {
        dim3 tg(H_ / 128, (NROW + 127) / 128, E_);
        gemm_f16_l1<<<tg, 256>>>(ddih, w1h, eb1, gates, hid, NROW);
    }
    {
        dim3 tg(1, (NROW + 127) / 128, 8);
        gemm_f16_l2<<<tg, 256>>>(hid, w2p, eb2, gates, out, NROW);
    }
}

// round 12
// speedup vs baseline: 1.4631x; 1.0101x over previous
#include <cuda_runtime.h>
#include <cuda_fp16.h>
#include <cstdint>

// ---------------- problem constants ----------------
#define B_    32
#define L_    336
#define C_    321
#define P_    96
#define E_    4
#define H_    2048
#define PATCH 12
#define NROW  (B_*C_)          // 10272
#define KTOT  (E_*H_)          // 8192
#define INV_  0.99999499987499937f   // 1/sqrt(1+1e-5)

// ---------------- scratch (static device globals; no allocation) ----------------
__device__ float  g_h  [NROW*L_];
__device__ float  g_s2 [NROW*168];
__device__ float  g_s4 [NROW*84];
__device__ float  g_s8 [NROW*42];
__device__ float  g_t  [NROW*168];
__device__ float  g_cur[NROW*L_];
__device__ float  g_te [NROW*L_];
__device__ float  g_d  [NROW*L_];
__device__ __half g_ddih[NROW*L_];             // fp16 ddi (scan writes half)
__device__ __half g_w1h[E_*H_*L_];             // fp16 ew1 (5.5 MB)
__device__ float  g_gates[NROW*E_];
__device__ __half g_hid[(size_t)NROW*KTOT];    // 168 MB fp16
__device__ __half g_w2p[P_*KTOT];              // repacked fp16 ew2

__device__ __forceinline__ float gelu_f(float x) {
    return 0.5f * x * (1.0f + erff(x * 0.70710678118654752f));
}

// ---------------- fp16 mma helpers ----------------
__device__ __forceinline__ void mma_f16(float* c, const uint32_t* a, const uint32_t* b) {
    asm volatile(
        "mma.sync.aligned.m16n8k16.row.col.f32.f16.f16.f32 "
        "{%0,%1,%2,%3}, {%4,%5,%6,%7}, {%8,%9}, {%0,%1,%2,%3};"
        : "+f"(c[0]), "+f"(c[1]), "+f"(c[2]), "+f"(c[3])
        : "r"(a[0]), "r"(a[1]), "r"(a[2]), "r"(a[3]), "r"(b[0]), "r"(b[1]));
}
__device__ __forceinline__ void ldsm_x4(uint32_t& r0, uint32_t& r1, uint32_t& r2, uint32_t& r3,
                                        uint32_t saddr) {
    asm volatile("ldmatrix.sync.aligned.m8n8.x4.shared.b16 {%0,%1,%2,%3}, [%4];"
                 : "=r"(r0), "=r"(r1), "=r"(r2), "=r"(r3) : "r"(saddr));
}
__device__ __forceinline__ uint32_t smem_u32(const void* p) {
    return (uint32_t)__cvta_generic_to_shared(p);
}
__device__ __forceinline__ void cp_async16(void* smem, const void* gmem, int bytes) {
    uint32_t saddr = smem_u32(smem);
    asm volatile("cp.async.ca.shared.global [%0], [%1], 16, %2;"
                 :: "r"(saddr), "l"(gmem), "r"(bytes));
}
__device__ __forceinline__ void cp_commit() { asm volatile("cp.async.commit_group;"); }
template<int N> __device__ __forceinline__ void cp_wait() {
    asm volatile("cp.async.wait_group %0;" :: "n"(N));
}

// ---------------- fp32 -> fp16 convert (elementwise) ----------------
__global__ void f2h_kernel(const float* __restrict__ in, __half* __restrict__ out, int n)
{
    int idx = blockIdx.x * blockDim.x + threadIdx.x;
    if (idx < n) out[idx] = __float2half_rn(in[idx]);
}

// ================= expert layer-1: fp16 m16n8k16 GEMM, 3-stage pipeline =================
// hid[row, e*H + n] = half( gates[row,e] * gelu( A[row,:336] @ W_e[n,:336]^T + eb1_e[n] ) )
// BM=128, BN=128, BK=16, 256 threads, 8 warps 4x2, warp tile 32x64. One barrier/iter.
__global__ void __launch_bounds__(256) gemm_f16_l1(
    const __half* __restrict__ A,     // NROW x 336
    const __half* __restrict__ W1,    // (E, 2048, 336)
    const float* __restrict__ eb1,    // (E, 2048)
    const float* __restrict__ gates,  // (NROW, 4)
    __half* __restrict__ hid,         // NROW x 8192
    int M)
{
    constexpr int KK = L_;            // 336
    constexpr int NK = KK / 16;       // 21
    __shared__ __align__(16) __half As[3][128][24];
    __shared__ __align__(16) __half Ws[3][128][24];

    int tid = threadIdx.x;
    int e   = blockIdx.z;
    const __half* W   = W1 + (size_t)e * H_ * KK;
    const float* bias = eb1 + (size_t)e * H_;
    int rowBase = blockIdx.y * 128;
    int colBase = blockIdx.x * 128;
    int lane = tid & 31, warp = tid >> 5;
    int g = lane >> 2, t4 = lane & 3;
    int wm0 = (warp >> 1) * 32, wn0 = (warp & 1) * 64;

    uint32_t aBase[3] = { smem_u32(&As[0][0][0]), smem_u32(&As[1][0][0]), smem_u32(&As[2][0][0]) };
    uint32_t bBase[3] = { smem_u32(&Ws[0][0][0]), smem_u32(&Ws[1][0][0]), smem_u32(&Ws[2][0][0]) };
    uint32_t aOff = (uint32_t)(((wm0 + (lane & 15)) * 24 + ((lane >> 4) << 3)) * 2);
    uint32_t bOff = (uint32_t)(((wn0 + (lane & 7) + ((lane >> 4) << 3)) * 24
                               + (((lane >> 3) & 1) << 3)) * 2);

    float acc[2][8][4];
    #pragma unroll
    for (int i = 0; i < 2; i++)
        #pragma unroll
        for (int j = 0; j < 8; j++)
            #pragma unroll
            for (int q = 0; q < 4; q++) acc[i][j][q] = 0.f;

    auto load_tile = [&](int it, int s) {
        int k0 = it * 16;
        int r = tid >> 1, j = tid & 1;       // 128 rows x 2 chunks of 8 halves
        int gm = rowBase + r;
        int gmc = gm < M ? gm : (M - 1);
        cp_async16(&As[s][r][j * 8],
                   A + (size_t)gmc * KK + k0 + j * 8,
                   gm < M ? 16 : 0);
        cp_async16(&Ws[s][r][j * 8],
                   W + (size_t)(colBase + r) * KK + k0 + j * 8, 16);
        cp_commit();
    };

    load_tile(0, 0);
    load_tile(1, 1);
    for (int it = 0; it < NK; it++) {
        int s = it % 3;
        if (it + 1 < NK) cp_wait<1>(); else cp_wait<0>();
        __syncthreads();
        if (it + 2 < NK) load_tile(it + 2, (it + 2) % 3);
        {
            uint32_t afr[2][4], bfr[8][2];
            #pragma unroll
            for (int mt = 0; mt < 2; mt++)
                ldsm_x4(afr[mt][0], afr[mt][1], afr[mt][2], afr[mt][3],
                        aBase[s] + aOff + (uint32_t)(mt * 768));
            #pragma unroll
            for (int np = 0; np < 4; np++)
                ldsm_x4(bfr[2 * np][0], bfr[2 * np][1], bfr[2 * np + 1][0], bfr[2 * np + 1][1],
                        bBase[s] + bOff + (uint32_t)(np * 768));
            #pragma unroll
            for (int mt = 0; mt < 2; mt++)
                #pragma unroll
                for (int nt = 0; nt < 8; nt++)
                    mma_f16(acc[mt][nt], afr[mt], bfr[nt]);
        }
    }

    #pragma unroll
    for (int mt = 0; mt < 2; mt++) {
        int r0 = rowBase + wm0 + mt * 16 + g;
        int r1 = r0 + 8;
        float g0 = (r0 < M) ? gates[r0 * 4 + e] : 0.f;
        float g1 = (r1 < M) ? gates[r1 * 4 + e] : 0.f;
        #pragma unroll
        for (int nt = 0; nt < 8; nt++) {
            int c0 = colBase + wn0 + nt * 8 + 2 * t4;
            float b0v = bias[c0], b1v = bias[c0 + 1];
            if (r0 < M) {
                __half2* p = (__half2*)(hid + (size_t)r0 * KTOT + (size_t)e * H_ + c0);
                *p = __floats2half2_rn(gelu_f(acc[mt][nt][0] + b0v) * g0,
                                       gelu_f(acc[mt][nt][1] + b1v) * g0);
            }
            if (r1 < M) {
                __half2* p = (__half2*)(hid + (size_t)r1 * KTOT + (size_t)e * H_ + c0);
                *p = __floats2half2_rn(gelu_f(acc[mt][nt][2] + b0v) * g1,
                                       gelu_f(acc[mt][nt][3] + b1v) * g1);
            }
        }
    }
}

// ================= expert layer-2: fp16 m16n8k16 split-K GEMM, 3-stage pipeline =================
__global__ void __launch_bounds__(256) gemm_f16_l2(
    const __half* __restrict__ A,    // NROW x 8192 (g_hid)
    const __half* __restrict__ W,    // 96 x 8192 (g_w2p)
    const float* __restrict__ eb2,   // (4,96)
    const float* __restrict__ gates, // (NROW,4)
    float* __restrict__ Out,         // (B,96,C)
    int M)
{
    constexpr int NSPLIT = 8, KC = KTOT / NSPLIT;   // 1024
    constexpr int NK = KC / 16;                      // 64
    __shared__ __align__(16) __half As[3][128][24];
    __shared__ __align__(16) __half Ws[3][96][24];

    int tid = threadIdx.x;
    int rowBase = blockIdx.y * 128;
    int kBase = blockIdx.z * KC;
    int lane = tid & 31, warp = tid >> 5;
    int g = lane >> 2, t4 = lane & 3;
    int wm0 = (warp >> 1) * 32, wn0 = (warp & 1) * 48;

    uint32_t aBase[3] = { smem_u32(&As[0][0][0]), smem_u32(&As[1][0][0]), smem_u32(&As[2][0][0]) };
    uint32_t bBase[3] = { smem_u32(&Ws[0][0][0]), smem_u32(&Ws[1][0][0]), smem_u32(&Ws[2][0][0]) };
    uint32_t aOff = (uint32_t)(((wm0 + (lane & 15)) * 24 + ((lane >> 4) << 3)) * 2);
    uint32_t bOff = (uint32_t)(((wn0 + (lane & 7) + ((lane >> 4) << 3)) * 24
                               + (((lane >> 3) & 1) << 3)) * 2);

    float acc[2][6][4];
    #pragma unroll
    for (int i = 0; i < 2; i++)
        #pragma unroll
        for (int j = 0; j < 6; j++)
            #pragma unroll
            for (int q = 0; q < 4; q++) acc[i][j][q] = 0.f;

    auto load_tile = [&](int it, int s) {
        int k0 = kBase + it * 16;
        int r = tid >> 1, j = tid & 1;
        int gm = rowBase + r;
        int gmc = gm < M ? gm : (M - 1);
        cp_async16(&As[s][r][j * 8],
                   A + (size_t)gmc * KTOT + k0 + j * 8,
                   gm < M ? 16 : 0);
        if (r < 96)
            cp_async16(&Ws[s][r][j * 8],
                       W + (size_t)r * KTOT + k0 + j * 8, 16);
        cp_commit();
    };

    load_tile(0, 0);
    load_tile(1, 1);
    for (int it = 0; it < NK; it++) {
        int s = it % 3;
        if (it + 1 < NK) cp_wait<1>(); else cp_wait<0>();
        __syncthreads();
        if (it + 2 < NK) load_tile(it + 2, (it + 2) % 3);
        {
            uint32_t afr[2][4], bfr[6][2];
            #pragma unroll
            for (int mt = 0; mt < 2; mt++)
                ldsm_x4(afr[mt][0], afr[mt][1], afr[mt][2], afr[mt][3],
                        aBase[s] + aOff + (uint32_t)(mt * 768));
            #pragma unroll
            for (int np = 0; np < 3; np++)
                ldsm_x4(bfr[2 * np][0], bfr[2 * np][1], bfr[2 * np + 1][0], bfr[2 * np + 1][1],
                        bBase[s] + bOff + (uint32_t)(np * 768));
            #pragma unroll
            for (int mt = 0; mt < 2; mt++)
                #pragma unroll
                for (int nt = 0; nt < 6; nt++)
                    mma_f16(acc[mt][nt], afr[mt], bfr[nt]);
        }
    }

    #pragma unroll
    for (int mt = 0; mt < 2; mt++) {
        int rr[2] = { rowBase + wm0 + mt * 16 + g, rowBase + wm0 + mt * 16 + g + 8 };
        #pragma unroll
        for (int hh = 0; hh < 2; hh++) {
            int gm = rr[hh];
            if (gm >= M) continue;
            int bb = gm / C_, cc = gm % C_;
            #pragma unroll
            for (int nt = 0; nt < 6; nt++) {
                int c0 = wn0 + nt * 8 + 2 * t4;
                #pragma unroll
                for (int q = 0; q < 2; q++) {
                    int gn = c0 + q;
                    float v = acc[mt][nt][hh * 2 + q];
                    if (blockIdx.z == 0) {
                        float bsum = 0.f;
                        #pragma unroll
                        for (int ee = 0; ee < E_; ee++)
                            bsum += gates[gm * 4 + ee] * eb2[ee * P_ + gn];
                        v += bsum;
                    }
                    atomicAdd(&Out[((size_t)bb * P_ + gn) * C_ + cc], v);
                }
            }
        }
    }
}

// ---------------- bn + transpose: x (B,L,C) -> h (B,C,L) with mdm_bn ----------------
__global__ void bn_transpose_kernel(const float* __restrict__ x,
                                    const float* __restrict__ w,
                                    const float* __restrict__ b,
                                    float* __restrict__ h)
{
    __shared__ float tile[32][33];
    int bi = blockIdx.z;
    int l0 = blockIdx.x * 32;
    int c0 = blockIdx.y * 32;
    int tx = threadIdx.x, ty = threadIdx.y;   // 32 x 8
    #pragma unroll
    for (int i = 0; i < 32; i += 8) {
        int l = l0 + ty + i, c = c0 + tx;
        tile[ty + i][tx] = (l < L_ && c < C_) ? x[((size_t)bi * L_ + l) * C_ + c] : 0.f;
    }
    __syncthreads();
    #pragma unroll
    for (int i = 0; i < 32; i += 8) {
        int c = c0 + ty + i, l = l0 + tx;
        if (c < C_ && l < L_) {
            float v = tile[tx][ty + i];
            int wi = c * L_ + l;
            h[((size_t)bi * C_ + c) * L_ + l] = v * (w[wi] * INV_) + b[wi];
        }
    }
}

// ---------------- avg-pool by 2 along last dim ----------------
__global__ void pool2_kernel(const float* __restrict__ in, float* __restrict__ out, int Lout)
{
    int idx = blockIdx.x * blockDim.x + threadIdx.x;
    int total = NROW * Lout;
    if (idx >= total) return;
    int r = idx / Lout, j = idx % Lout;
    const float* p = in + (size_t)r * 2 * Lout + 2 * j;
    out[idx] = 0.5f * (p[0] + p[1]);
}

// ---------------- mixer fp32 GEMM, BM=64 x BN=64 tiles ----------------
template<int ACT>
__global__ void __launch_bounds__(256) gemm_m(
    const float* __restrict__ A, int lda,
    const float* __restrict__ W,
    const float* __restrict__ bias,
    const float* __restrict__ resid,
    float* __restrict__ Cout, int ldc,
    int M, int N, int K)
{
    constexpr int BM = 64, BN = 64, BK = 16, TM = 4, TN = 4;
    __shared__ __align__(16) float As[BK][BM + 4];
    __shared__ __align__(16) float Ws[BK][BN + 4];
    int tid = threadIdx.x;
    int ty = tid >> 4, tx = tid & 15;          // 16 x 16 threads
    int rowBase = blockIdx.y * BM, colBase = blockIdx.x * BN;
    float acc[TM][TN] = {};

    for (int k0 = 0; k0 < K; k0 += BK) {
        #pragma unroll
        for (int i = 0; i < 4; i++) {
            int idx = tid + 256 * i;          // 0..1023
            int m = idx >> 4, kk = idx & 15;
            int gk = k0 + kk;
            int gm = rowBase + m;
            As[kk][m] = (gm < M && gk < K) ? A[(size_t)gm * lda + gk] : 0.f;
            int gn = colBase + m;
            Ws[kk][m] = (gn < N && gk < K) ? W[(size_t)gn * K + gk] : 0.f;
        }
        __syncthreads();
        #pragma unroll
        for (int kk = 0; kk < BK; kk++) {
            float a[TM], bf[TN];
            *(float4*)&a[0]  = *(const float4*)&As[kk][ty * TM];
            *(float4*)&bf[0] = *(const float4*)&Ws[kk][tx * TN];
            #pragma unroll
            for (int i = 0; i < TM; i++)
                #pragma unroll
                for (int j = 0; j < TN; j++)
                    acc[i][j] += a[i] * bf[j];
        }
        __syncthreads();
    }

    #pragma unroll
    for (int i = 0; i < TM; i++) {
        int gm = rowBase + ty * TM + i;
        if (gm >= M) continue;
        #pragma unroll
        for (int j = 0; j < TN; j++) {
            int gn = colBase + tx * TN + j;
            if (gn >= N) continue;
            float v = acc[i][j] + (bias ? bias[gn] : 0.f);
            if (ACT == 1) v = gelu_f(v);
            if (resid) v += resid[(size_t)gm * N + gn];
            Cout[(size_t)gm * ldc + gn] = v;
        }
    }
}

// ---------------- gating ----------------
__global__ void gate_kernel(const float* __restrict__ te,
                            const float* __restrict__ gw,
                            const float* __restrict__ gb,
                            float* __restrict__ gates)
{
    int warp = (blockIdx.x * blockDim.x + threadIdx.x) >> 5;
    int lane = threadIdx.x & 31;
    if (warp >= NROW) return;
    const float* row = te + (size_t)warp * L_;
    float acc[E_] = {0.f, 0.f, 0.f, 0.f};
    for (int l = lane; l < L_; l += 32) {
        float xv = row[l];
        #pragma unroll
        for (int e = 0; e < E_; e++) acc[e] += xv * gw[e * L_ + l];
    }
    #pragma unroll
    for (int off = 16; off; off >>= 1)
        #pragma unroll
        for (int e = 0; e < E_; e++)
            acc[e] += __shfl_xor_sync(0xffffffffu, acc[e], off);
    if (lane == 0) {
        float lg[E_], arr[E_];
        #pragma unroll
        for (int e = 0; e < E_; e++) { lg[e] = acc[e] + gb[e]; arr[e] = lg[e]; }
        #pragma unroll
        for (int i = 0; i < 3; i++)
            #pragma unroll
            for (int j = 0; j < 3; j++)
                if (arr[j] > arr[j + 1]) { float tmp = arr[j]; arr[j] = arr[j + 1]; arr[j + 1] = tmp; }
        float kth = arr[E_ - 2];
        float mx = lg[0];
        #pragma unroll
        for (int e = 1; e < E_; e++) mx = fmaxf(mx, lg[e]);
        float s[E_], ssum = 0.f;
        #pragma unroll
        for (int e = 0; e < E_; e++) { s[e] = expf(lg[e] - mx); ssum += s[e]; }
        #pragma unroll
        for (int e = 0; e < E_; e++) s[e] /= ssum;
        float dec[E_];
        #pragma unroll
        for (int e = 0; e < E_; e++)
            dec[e] = (lg[e] < kth) ? 10.f * logf(s[e] + 1.f) : 10.f * (expf(s[e]) - 1.f);
        float m2 = dec[0];
        #pragma unroll
        for (int e = 1; e < E_; e++) m2 = fmaxf(m2, dec[e]);
        float t2[E_], su = 0.f;
        #pragma unroll
        for (int e = 0; e < E_; e++) { t2[e] = expf(dec[e] - m2); su += t2[e]; }
        #pragma unroll
        for (int e = 0; e < E_; e++) gates[(size_t)warp * E_ + e] = t2[e] / su;
    }
}

// ---------------- ddi bn ----------------
__global__ void bn_ddi_kernel(const float* __restrict__ te,
                              const float* __restrict__ w,
                              const float* __restrict__ b,
                              float* __restrict__ out)
{
    int idx = blockIdx.x * blockDim.x + threadIdx.x;
    if (idx >= NROW * L_) return;
    int l = idx % L_;
    int c = (idx / L_) % C_;
    int wi = c * L_ + l;
    out[idx] = te[idx] * (w[wi] * INV_) + b[wi];
}

// ---------------- ddi sequential scan (writes fp16 output) ----------------
__global__ void ddi_scan_kernel(const float* __restrict__ d,
                                const float* __restrict__ n1w,
                                const float* __restrict__ n1b,
                                const float* __restrict__ agg_w,
                                const float* __restrict__ agg_b,
                                __half* __restrict__ out)
{
    __shared__ float aw[PATCH * PATCH];
    __shared__ float ab[PATCH];
    for (int i = threadIdx.x; i < PATCH * PATCH; i += blockDim.x) aw[i] = agg_w[i];
    for (int i = threadIdx.x; i < PATCH; i += blockDim.x) ab[i] = agg_b[i];
    __syncthreads();
    int row = blockIdx.x * blockDim.x + threadIdx.x;
    if (row >= NROW) return;
    int c = row % C_;
    float w[PATCH], bb[PATCH], prev[PATCH];
    #pragma unroll
    for (int p = 0; p < PATCH; p++) {
        w[p]  = n1w[c * PATCH + p] * INV_;
        bb[p] = n1b[c * PATCH + p];
    }
    const float* drow = d + (size_t)row * L_;
    __half* orow = out + (size_t)row * L_;
    #pragma unroll
    for (int p = 0; p < PATCH; p++) {
        prev[p] = drow[p];
        orow[p] = __float2half_rn(prev[p]);
    }
    for (int t = 1; t < L_ / PATCH; t++) {
        float inp[PATCH], tmp[PATCH];
        #pragma unroll
        for (int p = 0; p < PATCH; p++) inp[p] = prev[p] * w[p] + bb[p];
        #pragma unroll
        for (int m = 0; m < PATCH; m++) {
            float s = ab[m];
            #pragma unroll
            for (int p = 0; p < PATCH; p++) s += inp[p] * aw[m * PATCH + p];
            tmp[m] = gelu_f(s);
        }
        #pragma unroll
        for (int p = 0; p < PATCH; p++) {
            prev[p] = tmp[p] + drow[t * PATCH + p];
            orow[t * PATCH + p] = __float2half_rn(prev[p]);
        }
    }
}

// ---------------- repack ew2 (E,P,H) -> (P, E*H), fp16 ----------------
__global__ void repack_w2_kernel(const float* __restrict__ ew2, __half* __restrict__ w2p)
{
    int idx = blockIdx.x * blockDim.x + threadIdx.x;
    if (idx >= P_ * KTOT) return;
    int p = idx / KTOT;
    int r = idx % KTOT;
    int e = r / H_, hh = r % H_;
    w2p[idx] = __float2half_rn(ew2[((size_t)e * P_ + p) * H_ + hh]);
}

__global__ void zero_kernel(float* o, int n)
{
    int idx = blockIdx.x * blockDim.x + threadIdx.x;
    if (idx < n) o[idx] = 0.f;
}

// ---------------- launch ----------------
extern "C" void kernel_launch(void* const* d_in, const int* in_sizes, int n_in,
                              void* d_out, int out_size)
{
    // Map inputs, skipping the scalar 'k' (size 1) wherever it sits.
    const float* in[27];
    int pi = 0;
    for (int i = 0; i < n_in && pi < 27; i++) {
        if (in_sizes[i] == 1) continue;
        in[pi++] = (const float*)d_in[i];
    }
    const float* x    = in[0];
    const float* mdw  = in[1];  const float* mdb  = in[2];
    const float* w1s[3] = { in[3], in[7],  in[11] };
    const float* b1s[3] = { in[4], in[8],  in[12] };
    const float* w2s[3] = { in[5], in[9],  in[13] };
    const float* b2s[3] = { in[6], in[10], in[14] };
    const float* ddw  = in[15]; const float* ddb  = in[16];
    const float* n1w  = in[17]; const float* n1b  = in[18];
    const float* aggw = in[19]; const float* aggb = in[20];
    const float* gw   = in[21]; const float* gb   = in[22];
    const float* ew1  = in[23]; const float* eb1  = in[24];
    const float* ew2  = in[25]; const float* eb2  = in[26];

    float *h, *s2, *s4, *s8, *t, *cur, *te, *dd, *gates;
    __half *ddih, *w1h, *hid, *w2p;
    cudaGetSymbolAddress((void**)&h,    g_h);
    cudaGetSymbolAddress((void**)&s2,   g_s2);
    cudaGetSymbolAddress((void**)&s4,   g_s4);
    cudaGetSymbolAddress((void**)&s8,   g_s8);
    cudaGetSymbolAddress((void**)&t,    g_t);
    cudaGetSymbolAddress((void**)&cur,  g_cur);
    cudaGetSymbolAddress((void**)&te,   g_te);
    cudaGetSymbolAddress((void**)&dd,   g_d);
    cudaGetSymbolAddress((void**)&ddih, g_ddih);
    cudaGetSymbolAddress((void**)&w1h,  g_w1h);
    cudaGetSymbolAddress((void**)&gates,g_gates);
    cudaGetSymbolAddress((void**)&hid,  g_hid);
    cudaGetSymbolAddress((void**)&w2p,  g_w2p);

    float* out = (float*)d_out;

    // 1) bn + transpose -> h (B,C,L)
    {
        dim3 tb(32, 8);
        dim3 tg((L_ + 31) / 32, (C_ + 31) / 32, B_);
        bn_transpose_kernel<<<tg, tb>>>(x, mdw, mdb, h);
    }
    // 2) pools
    pool2_kernel<<<(NROW * 168 + 255) / 256, 256>>>(h,  s2, 168);
    pool2_kernel<<<(NROW * 84  + 255) / 256, 256>>>(s2, s4, 84);
    pool2_kernel<<<(NROW * 42  + 255) / 256, 256>>>(s4, s8, 42);

    // 3) mixer stages (fp32, 64x64 tiles)
    auto mgrid = [](int M, int N) { return dim3((N + 63) / 64, (M + 63) / 64); };
    gemm_m<1><<<mgrid(NROW, 42), 256>>>(s8, 42, w1s[0], b1s[0], nullptr, t,   42,  NROW, 42,  42);
    gemm_m<0><<<mgrid(NROW, 84), 256>>>(t,  42, w2s[0], b2s[0], s4,      cur, 84,  NROW, 84,  42);
    gemm_m<1><<<mgrid(NROW, 84), 256>>>(cur,84, w1s[1], b1s[1], nullptr, t,   84,  NROW, 84,  84);
    gemm_m<0><<<mgrid(NROW,168), 256>>>(t,  84, w2s[1], b2s[1], s2,      cur, 168, NROW, 168, 84);
    gemm_m<1><<<mgrid(NROW,168), 256>>>(cur,168,w1s[2], b1s[2], nullptr, t,   168, NROW, 168, 168);
    gemm_m<0><<<mgrid(NROW,336), 256>>>(t,  168,w2s[2], b2s[2], h,       te,  336, NROW, 336, 168);

    // 4) gating from te
    gate_kernel<<<(NROW * 32 + 255) / 256, 256>>>(te, gw, gb, gates);

    // 5) ddi: bn then 27-step scan (scan emits fp16 ddi directly)
    bn_ddi_kernel<<<(NROW * L_ + 255) / 256, 256>>>(te, ddw, ddb, dd);
    ddi_scan_kernel<<<(NROW + 127) / 128, 128>>>(dd, n1w, n1b, aggw, aggb, ddih);

    // 6) convert expert weights to fp16
    f2h_kernel<<<(E_ * H_ * L_ + 255) / 256, 256>>>(ew1, w1h, E_ * H_ * L_);
    repack_w2_kernel<<<(P_ * KTOT + 255) / 256, 256>>>(ew2, w2p);
    zero_kernel<<<(out_size + 255) / 256, 256>>>(out, out_size);

    // 7) experts — fp16 m16n8k16, 3-stage cp.async pipeline (1 barrier/iter)
    {
        dim3 tg(H_ / 128, (NROW + 127) / 128, E_);
        gemm_f16_l1<<<tg, 256>>>(ddih, w1h, eb1, gates, hid, NROW);
    }
    {
        dim3 tg(1, (NROW + 127) / 128, 8);
        gemm_f16_l2<<<tg, 256>>>(hid, w2p, eb2, gates, out, NROW);
    }
}

// round 13
// speedup vs baseline: 1.5951x; 1.0902x over previous
#include <cuda_runtime.h>
#include <cuda_fp16.h>
#include <cstdint>

// ---------------- problem constants ----------------
#define B_    32
#define L_    336
#define C_    321
#define P_    96
#define E_    4
#define H_    2048
#define PATCH 12
#define NROW  (B_*C_)          // 10272
#define KTOT  (E_*H_)          // 8192
#define INV_  0.99999499987499937f   // 1/sqrt(1+1e-5)

// ---------------- scratch (static device globals; no allocation) ----------------
__device__ float  g_h  [NROW*L_];
__device__ float  g_s2 [NROW*168];
__device__ float  g_s4 [NROW*84];
__device__ float  g_s8 [NROW*42];
__device__ float  g_t  [NROW*168];
__device__ float  g_cur[NROW*L_];
__device__ float  g_te [NROW*L_];
__device__ __half g_ddih[NROW*L_];             // fp16 ddi (scan writes half)
__device__ __half g_w1h[E_*H_*L_];             // fp16 ew1 (5.5 MB)
__device__ float  g_gates[NROW*E_];
__device__ __half g_hid[(size_t)NROW*KTOT];    // 168 MB fp16
__device__ __half g_w2p[P_*KTOT];              // repacked fp16 ew2

__device__ __forceinline__ float gelu_f(float x) {
    return 0.5f * x * (1.0f + erff(x * 0.70710678118654752f));
}

// ---------------- fp16 mma helpers ----------------
__device__ __forceinline__ void mma_f16(float* c, const uint32_t* a, const uint32_t* b) {
    asm volatile(
        "mma.sync.aligned.m16n8k16.row.col.f32.f16.f16.f32 "
        "{%0,%1,%2,%3}, {%4,%5,%6,%7}, {%8,%9}, {%0,%1,%2,%3};"
        : "+f"(c[0]), "+f"(c[1]), "+f"(c[2]), "+f"(c[3])
        : "r"(a[0]), "r"(a[1]), "r"(a[2]), "r"(a[3]), "r"(b[0]), "r"(b[1]));
}
__device__ __forceinline__ void ldsm_x4(uint32_t& r0, uint32_t& r1, uint32_t& r2, uint32_t& r3,
                                        uint32_t saddr) {
    asm volatile("ldmatrix.sync.aligned.m8n8.x4.shared.b16 {%0,%1,%2,%3}, [%4];"
                 : "=r"(r0), "=r"(r1), "=r"(r2), "=r"(r3) : "r"(saddr));
}
__device__ __forceinline__ uint32_t smem_u32(const void* p) {
    return (uint32_t)__cvta_generic_to_shared(p);
}
__device__ __forceinline__ void cp_async16(void* smem, const void* gmem, int bytes) {
    uint32_t saddr = smem_u32(smem);
    asm volatile("cp.async.ca.shared.global [%0], [%1], 16, %2;"
                 :: "r"(saddr), "l"(gmem), "r"(bytes));
}
__device__ __forceinline__ void cp_commit() { asm volatile("cp.async.commit_group;"); }
template<int N> __device__ __forceinline__ void cp_wait() {
    asm volatile("cp.async.wait_group %0;" :: "n"(N));
}

// ================= expert layer-1: fp16 m16n8k16 GEMM, 3-stage pipeline (R12) =================
__global__ void __launch_bounds__(256) gemm_f16_l1(
    const __half* __restrict__ A,     // NROW x 336
    const __half* __restrict__ W1,    // (E, 2048, 336)
    const float* __restrict__ eb1,    // (E, 2048)
    const float* __restrict__ gates,  // (NROW, 4)
    __half* __restrict__ hid,         // NROW x 8192
    int M)
{
    constexpr int KK = L_;            // 336
    constexpr int NK = KK / 16;       // 21
    __shared__ __align__(16) __half As[3][128][24];
    __shared__ __align__(16) __half Ws[3][128][24];

    int tid = threadIdx.x;
    int e   = blockIdx.z;
    const __half* W   = W1 + (size_t)e * H_ * KK;
    const float* bias = eb1 + (size_t)e * H_;
    int rowBase = blockIdx.y * 128;
    int colBase = blockIdx.x * 128;
    int lane = tid & 31, warp = tid >> 5;
    int g = lane >> 2, t4 = lane & 3;
    int wm0 = (warp >> 1) * 32, wn0 = (warp & 1) * 64;

    uint32_t aBase[3] = { smem_u32(&As[0][0][0]), smem_u32(&As[1][0][0]), smem_u32(&As[2][0][0]) };
    uint32_t bBase[3] = { smem_u32(&Ws[0][0][0]), smem_u32(&Ws[1][0][0]), smem_u32(&Ws[2][0][0]) };
    uint32_t aOff = (uint32_t)(((wm0 + (lane & 15)) * 24 + ((lane >> 4) << 3)) * 2);
    uint32_t bOff = (uint32_t)(((wn0 + (lane & 7) + ((lane >> 4) << 3)) * 24
                               + (((lane >> 3) & 1) << 3)) * 2);

    float acc[2][8][4];
    #pragma unroll
    for (int i = 0; i < 2; i++)
        #pragma unroll
        for (int j = 0; j < 8; j++)
            #pragma unroll
            for (int q = 0; q < 4; q++) acc[i][j][q] = 0.f;

    auto load_tile = [&](int it, int s) {
        int k0 = it * 16;
        int r = tid >> 1, j = tid & 1;
        int gm = rowBase + r;
        int gmc = gm < M ? gm : (M - 1);
        cp_async16(&As[s][r][j * 8],
                   A + (size_t)gmc * KK + k0 + j * 8,
                   gm < M ? 16 : 0);
        cp_async16(&Ws[s][r][j * 8],
                   W + (size_t)(colBase + r) * KK + k0 + j * 8, 16);
        cp_commit();
    };

    load_tile(0, 0);
    load_tile(1, 1);
    for (int it = 0; it < NK; it++) {
        int s = it % 3;
        if (it + 1 < NK) cp_wait<1>(); else cp_wait<0>();
        __syncthreads();
        if (it + 2 < NK) load_tile(it + 2, (it + 2) % 3);
        {
            uint32_t afr[2][4], bfr[8][2];
            #pragma unroll
            for (int mt = 0; mt < 2; mt++)
                ldsm_x4(afr[mt][0], afr[mt][1], afr[mt][2], afr[mt][3],
                        aBase[s] + aOff + (uint32_t)(mt * 768));
            #pragma unroll
            for (int np = 0; np < 4; np++)
                ldsm_x4(bfr[2 * np][0], bfr[2 * np][1], bfr[2 * np + 1][0], bfr[2 * np + 1][1],
                        bBase[s] + bOff + (uint32_t)(np * 768));
            #pragma unroll
            for (int mt = 0; mt < 2; mt++)
                #pragma unroll
                for (int nt = 0; nt < 8; nt++)
                    mma_f16(acc[mt][nt], afr[mt], bfr[nt]);
        }
    }

    #pragma unroll
    for (int mt = 0; mt < 2; mt++) {
        int r0 = rowBase + wm0 + mt * 16 + g;
        int r1 = r0 + 8;
        float g0 = (r0 < M) ? gates[r0 * 4 + e] : 0.f;
        float g1 = (r1 < M) ? gates[r1 * 4 + e] : 0.f;
        #pragma unroll
        for (int nt = 0; nt < 8; nt++) {
            int c0 = colBase + wn0 + nt * 8 + 2 * t4;
            float b0v = bias[c0], b1v = bias[c0 + 1];
            if (r0 < M) {
                __half2* p = (__half2*)(hid + (size_t)r0 * KTOT + (size_t)e * H_ + c0);
                *p = __floats2half2_rn(gelu_f(acc[mt][nt][0] + b0v) * g0,
                                       gelu_f(acc[mt][nt][1] + b1v) * g0);
            }
            if (r1 < M) {
                __half2* p = (__half2*)(hid + (size_t)r1 * KTOT + (size_t)e * H_ + c0);
                *p = __floats2half2_rn(gelu_f(acc[mt][nt][2] + b0v) * g1,
                                       gelu_f(acc[mt][nt][3] + b1v) * g1);
            }
        }
    }
}

// ================= expert layer-2: fp16 m16n8k16 split-K GEMM, 3-stage pipeline (R12) =================
__global__ void __launch_bounds__(256) gemm_f16_l2(
    const __half* __restrict__ A,    // NROW x 8192 (g_hid)
    const __half* __restrict__ W,    // 96 x 8192 (g_w2p)
    const float* __restrict__ eb2,   // (4,96)
    const float* __restrict__ gates, // (NROW,4)
    float* __restrict__ Out,         // (B,96,C)
    int M)
{
    constexpr int NSPLIT = 8, KC = KTOT / NSPLIT;   // 1024
    constexpr int NK = KC / 16;                      // 64
    __shared__ __align__(16) __half As[3][128][24];
    __shared__ __align__(16) __half Ws[3][96][24];

    int tid = threadIdx.x;
    int rowBase = blockIdx.y * 128;
    int kBase = blockIdx.z * KC;
    int lane = tid & 31, warp = tid >> 5;
    int g = lane >> 2, t4 = lane & 3;
    int wm0 = (warp >> 1) * 32, wn0 = (warp & 1) * 48;

    uint32_t aBase[3] = { smem_u32(&As[0][0][0]), smem_u32(&As[1][0][0]), smem_u32(&As[2][0][0]) };
    uint32_t bBase[3] = { smem_u32(&Ws[0][0][0]), smem_u32(&Ws[1][0][0]), smem_u32(&Ws[2][0][0]) };
    uint32_t aOff = (uint32_t)(((wm0 + (lane & 15)) * 24 + ((lane >> 4) << 3)) * 2);
    uint32_t bOff = (uint32_t)(((wn0 + (lane & 7) + ((lane >> 4) << 3)) * 24
                               + (((lane >> 3) & 1) << 3)) * 2);

    float acc[2][6][4];
    #pragma unroll
    for (int i = 0; i < 2; i++)
        #pragma unroll
        for (int j = 0; j < 6; j++)
            #pragma unroll
            for (int q = 0; q < 4; q++) acc[i][j][q] = 0.f;

    auto load_tile = [&](int it, int s) {
        int k0 = kBase + it * 16;
        int r = tid >> 1, j = tid & 1;
        int gm = rowBase + r;
        int gmc = gm < M ? gm : (M - 1);
        cp_async16(&As[s][r][j * 8],
                   A + (size_t)gmc * KTOT + k0 + j * 8,
                   gm < M ? 16 : 0);
        if (r < 96)
            cp_async16(&Ws[s][r][j * 8],
                       W + (size_t)r * KTOT + k0 + j * 8, 16);
        cp_commit();
    };

    load_tile(0, 0);
    load_tile(1, 1);
    for (int it = 0; it < NK; it++) {
        int s = it % 3;
        if (it + 1 < NK) cp_wait<1>(); else cp_wait<0>();
        __syncthreads();
        if (it + 2 < NK) load_tile(it + 2, (it + 2) % 3);
        {
            uint32_t afr[2][4], bfr[6][2];
            #pragma unroll
            for (int mt = 0; mt < 2; mt++)
                ldsm_x4(afr[mt][0], afr[mt][1], afr[mt][2], afr[mt][3],
                        aBase[s] + aOff + (uint32_t)(mt * 768));
            #pragma unroll
            for (int np = 0; np < 3; np++)
                ldsm_x4(bfr[2 * np][0], bfr[2 * np][1], bfr[2 * np + 1][0], bfr[2 * np + 1][1],
                        bBase[s] + bOff + (uint32_t)(np * 768));
            #pragma unroll
            for (int mt = 0; mt < 2; mt++)
                #pragma unroll
                for (int nt = 0; nt < 6; nt++)
                    mma_f16(acc[mt][nt], afr[mt], bfr[nt]);
        }
    }

    #pragma unroll
    for (int mt = 0; mt < 2; mt++) {
        int rr[2] = { rowBase + wm0 + mt * 16 + g, rowBase + wm0 + mt * 16 + g + 8 };
        #pragma unroll
        for (int hh = 0; hh < 2; hh++) {
            int gm = rr[hh];
            if (gm >= M) continue;
            int bb = gm / C_, cc = gm % C_;
            #pragma unroll
            for (int nt = 0; nt < 6; nt++) {
                int c0 = wn0 + nt * 8 + 2 * t4;
                #pragma unroll
                for (int q = 0; q < 2; q++) {
                    int gn = c0 + q;
                    float v = acc[mt][nt][hh * 2 + q];
                    if (blockIdx.z == 0) {
                        float bsum = 0.f;
                        #pragma unroll
                        for (int ee = 0; ee < E_; ee++)
                            bsum += gates[gm * 4 + ee] * eb2[ee * P_ + gn];
                        v += bsum;
                    }
                    atomicAdd(&Out[((size_t)bb * P_ + gn) * C_ + cc], v);
                }
            }
        }
    }
}

// ---------------- bn + transpose: x (B,L,C) -> h (B,C,L) with mdm_bn ----------------
__global__ void bn_transpose_kernel(const float* __restrict__ x,
                                    const float* __restrict__ w,
                                    const float* __restrict__ b,
                                    float* __restrict__ h)
{
    __shared__ float tile[32][33];
    int bi = blockIdx.z;
    int l0 = blockIdx.x * 32;
    int c0 = blockIdx.y * 32;
    int tx = threadIdx.x, ty = threadIdx.y;   // 32 x 8
    #pragma unroll
    for (int i = 0; i < 32; i += 8) {
        int l = l0 + ty + i, c = c0 + tx;
        tile[ty + i][tx] = (l < L_ && c < C_) ? x[((size_t)bi * L_ + l) * C_ + c] : 0.f;
    }
    __syncthreads();
    #pragma unroll
    for (int i = 0; i < 32; i += 8) {
        int c = c0 + ty + i, l = l0 + tx;
        if (c < C_ && l < L_) {
            float v = tile[tx][ty + i];
            int wi = c * L_ + l;
            h[((size_t)bi * C_ + c) * L_ + l] = v * (w[wi] * INV_) + b[wi];
        }
    }
}

// ---------------- fused pool: h -> s2, s4, s8 in one pass ----------------
__global__ void pool_all_kernel(const float* __restrict__ h,
                                float* __restrict__ s2,
                                float* __restrict__ s4,
                                float* __restrict__ s8)
{
    int idx = blockIdx.x * blockDim.x + threadIdx.x;
    if (idx >= NROW * 42) return;
    int r = idx / 42, j = idx % 42;
    const float* p = h + (size_t)r * L_ + j * 8;
    float a0 = 0.5f * (p[0] + p[1]);
    float a1 = 0.5f * (p[2] + p[3]);
    float a2 = 0.5f * (p[4] + p[5]);
    float a3 = 0.5f * (p[6] + p[7]);
    float b0 = 0.5f * (a0 + a1);
    float b1 = 0.5f * (a2 + a3);
    float* q2 = s2 + (size_t)r * 168 + j * 4;
    q2[0] = a0; q2[1] = a1; q2[2] = a2; q2[3] = a3;
    float* q4 = s4 + (size_t)r * 84 + j * 2;
    q4[0] = b0; q4[1] = b1;
    s8[(size_t)r * 42 + j] = 0.5f * (b0 + b1);
}

// ---------------- mixer fp32 GEMM, BM=64 x BN=64 tiles ----------------
template<int ACT>
__global__ void __launch_bounds__(256) gemm_m(
    const float* __restrict__ A, int lda,
    const float* __restrict__ W,
    const float* __restrict__ bias,
    const float* __restrict__ resid,
    float* __restrict__ Cout, int ldc,
    int M, int N, int K)
{
    constexpr int BM = 64, BN = 64, BK = 16, TM = 4, TN = 4;
    __shared__ __align__(16) float As[BK][BM + 4];
    __shared__ __align__(16) float Ws[BK][BN + 4];
    int tid = threadIdx.x;
    int ty = tid >> 4, tx = tid & 15;
    int rowBase = blockIdx.y * BM, colBase = blockIdx.x * BN;
    float acc[TM][TN] = {};

    for (int k0 = 0; k0 < K; k0 += BK) {
        #pragma unroll
        for (int i = 0; i < 4; i++) {
            int idx = tid + 256 * i;
            int m = idx >> 4, kk = idx & 15;
            int gk = k0 + kk;
            int gm = rowBase + m;
            As[kk][m] = (gm < M && gk < K) ? A[(size_t)gm * lda + gk] : 0.f;
            int gn = colBase + m;
            Ws[kk][m] = (gn < N && gk < K) ? W[(size_t)gn * K + gk] : 0.f;
        }
        __syncthreads();
        #pragma unroll
        for (int kk = 0; kk < BK; kk++) {
            float a[TM], bf[TN];
            *(float4*)&a[0]  = *(const float4*)&As[kk][ty * TM];
            *(float4*)&bf[0] = *(const float4*)&Ws[kk][tx * TN];
            #pragma unroll
            for (int i = 0; i < TM; i++)
                #pragma unroll
                for (int j = 0; j < TN; j++)
                    acc[i][j] += a[i] * bf[j];
        }
        __syncthreads();
    }

    #pragma unroll
    for (int i = 0; i < TM; i++) {
        int gm = rowBase + ty * TM + i;
        if (gm >= M) continue;
        #pragma unroll
        for (int j = 0; j < TN; j++) {
            int gn = colBase + tx * TN + j;
            if (gn >= N) continue;
            float v = acc[i][j] + (bias ? bias[gn] : 0.f);
            if (ACT == 1) v = gelu_f(v);
            if (resid) v += resid[(size_t)gm * N + gn];
            Cout[(size_t)gm * ldc + gn] = v;
        }
    }
}

// ---------------- gating ----------------
__global__ void gate_kernel(const float* __restrict__ te,
                            const float* __restrict__ gw,
                            const float* __restrict__ gb,
                            float* __restrict__ gates)
{
    int warp = (blockIdx.x * blockDim.x + threadIdx.x) >> 5;
    int lane = threadIdx.x & 31;
    if (warp >= NROW) return;
    const float* row = te + (size_t)warp * L_;
    float acc[E_] = {0.f, 0.f, 0.f, 0.f};
    for (int l = lane; l < L_; l += 32) {
        float xv = row[l];
        #pragma unroll
        for (int e = 0; e < E_; e++) acc[e] += xv * gw[e * L_ + l];
    }
    #pragma unroll
    for (int off = 16; off; off >>= 1)
        #pragma unroll
        for (int e = 0; e < E_; e++)
            acc[e] += __shfl_xor_sync(0xffffffffu, acc[e], off);
    if (lane == 0) {
        float lg[E_], arr[E_];
        #pragma unroll
        for (int e = 0; e < E_; e++) { lg[e] = acc[e] + gb[e]; arr[e] = lg[e]; }
        #pragma unroll
        for (int i = 0; i < 3; i++)
            #pragma unroll
            for (int j = 0; j < 3; j++)
                if (arr[j] > arr[j + 1]) { float tmp = arr[j]; arr[j] = arr[j + 1]; arr[j + 1] = tmp; }
        float kth = arr[E_ - 2];
        float mx = lg[0];
        #pragma unroll
        for (int e = 1; e < E_; e++) mx = fmaxf(mx, lg[e]);
        float s[E_], ssum = 0.f;
        #pragma unroll
        for (int e = 0; e < E_; e++) { s[e] = expf(lg[e] - mx); ssum += s[e]; }
        #pragma unroll
        for (int e = 0; e < E_; e++) s[e] /= ssum;
        float dec[E_];
        #pragma unroll
        for (int e = 0; e < E_; e++)
            dec[e] = (lg[e] < kth) ? 10.f * logf(s[e] + 1.f) : 10.f * (expf(s[e]) - 1.f);
        float m2 = dec[0];
        #pragma unroll
        for (int e = 1; e < E_; e++) m2 = fmaxf(m2, dec[e]);
        float t2[E_], su = 0.f;
        #pragma unroll
        for (int e = 0; e < E_; e++) { t2[e] = expf(dec[e] - m2); su += t2[e]; }
        #pragma unroll
        for (int e = 0; e < E_; e++) gates[(size_t)warp * E_ + e] = t2[e] / su;
    }
}

// ---------------- fused bn + ddi scan, 16 lanes per row (12 active) ----------------
// dd[row,l] = te[row,l]*(ddw[c*L+l]*INV) + ddb[c*L+l], computed inline.
__global__ void __launch_bounds__(256) ddi_scan2_kernel(
    const float* __restrict__ te,
    const float* __restrict__ ddw,
    const float* __restrict__ ddb,
    const float* __restrict__ n1w,
    const float* __restrict__ n1b,
    const float* __restrict__ agg_w,
    const float* __restrict__ agg_b,
    __half* __restrict__ out)
{
    __shared__ float aw[PATCH * PATCH];
    __shared__ float ab[PATCH];
    for (int i = threadIdx.x; i < PATCH * PATCH; i += blockDim.x) aw[i] = agg_w[i];
    for (int i = threadIdx.x; i < PATCH; i += blockDim.x) ab[i] = agg_b[i];
    __syncthreads();

    int gid  = blockIdx.x * blockDim.x + threadIdx.x;
    int row  = gid >> 4;            // 16 lanes per row
    int lp   = gid & 15;            // lane-in-group; 0..11 active
    if (row >= NROW) return;
    int c = row % C_;
    int base16 = (threadIdx.x & 31) & ~15;   // group base within warp

    bool act = lp < PATCH;
    int lpc = act ? lp : 0;

    float w1 = n1w[c * PATCH + lpc] * INV_;
    float b1 = n1b[c * PATCH + lpc];

    const float* terow = te + (size_t)row * L_;
    const float* wrow  = ddw + (size_t)c * L_;
    const float* brow  = ddb + (size_t)c * L_;
    __half* orow = out + (size_t)row * L_;

    // t = 0
    float dv = terow[lpc] * (wrow[lpc] * INV_) + brow[lpc];
    float prev = dv;
    if (act) orow[lp] = __float2half_rn(prev);

    for (int t = 1; t < L_ / PATCH; t++) {
        float inp = prev * w1 + b1;
        // matvec: s_m = ab[m] + sum_p inp_p * aw[m][p]
        float s = ab[lpc];
        #pragma unroll
        for (int p = 0; p < PATCH; p++) {
            float v = __shfl_sync(0xffffffffu, inp, base16 + p, 32);
            s += v * aw[lpc * PATCH + p];
        }
        float tmp = gelu_f(s);
        int l = t * PATCH + lpc;
        float dnext = terow[l] * (wrow[l] * INV_) + brow[l];
        prev = tmp + dnext;
        if (act) orow[l] = __float2half_rn(prev);
    }
}

// ---------------- merged prep: f2h(ew1) + repack(ew2) + zero(out) ----------------
#define N_W1 (E_*H_*L_)      // 2752512
#define N_W2 (P_*KTOT)       // 786432
__global__ void prep_kernel(const float* __restrict__ ew1, __half* __restrict__ w1h,
                            const float* __restrict__ ew2, __half* __restrict__ w2p,
                            float* __restrict__ out, int out_n)
{
    int idx = blockIdx.x * blockDim.x + threadIdx.x;
    if (idx < N_W1) {
        w1h[idx] = __float2half_rn(ew1[idx]);
    }
    int i2 = idx - N_W1;
    if (i2 >= 0 && i2 < N_W2) {
        int p = i2 / KTOT;
        int r = i2 % KTOT;
        int e = r / H_, hh = r % H_;
        w2p[i2] = __float2half_rn(ew2[((size_t)e * P_ + p) * H_ + hh]);
    }
    int i3 = idx - N_W1 - N_W2;
    if (i3 >= 0 && i3 < out_n) out[i3] = 0.f;
}

// ---------------- launch ----------------
extern "C" void kernel_launch(void* const* d_in, const int* in_sizes, int n_in,
                              void* d_out, int out_size)
{
    // Map inputs, skipping the scalar 'k' (size 1) wherever it sits.
    const float* in[27];
    int pi = 0;
    for (int i = 0; i < n_in && pi < 27; i++) {
        if (in_sizes[i] == 1) continue;
        in[pi++] = (const float*)d_in[i];
    }
    const float* x    = in[0];
    const float* mdw  = in[1];  const float* mdb  = in[2];
    const float* w1s[3] = { in[3], in[7],  in[11] };
    const float* b1s[3] = { in[4], in[8],  in[12] };
    const float* w2s[3] = { in[5], in[9],  in[13] };
    const float* b2s[3] = { in[6], in[10], in[14] };
    const float* ddw  = in[15]; const float* ddb  = in[16];
    const float* n1w  = in[17]; const float* n1b  = in[18];
    const float* aggw = in[19]; const float* aggb = in[20];
    const float* gw   = in[21]; const float* gb   = in[22];
    const float* ew1  = in[23]; const float* eb1  = in[24];
    const float* ew2  = in[25]; const float* eb2  = in[26];

    float *h, *s2, *s4, *s8, *t, *cur, *te, *gates;
    __half *ddih, *w1h, *hid, *w2p;
    cudaGetSymbolAddress((void**)&h,    g_h);
    cudaGetSymbolAddress((void**)&s2,   g_s2);
    cudaGetSymbolAddress((void**)&s4,   g_s4);
    cudaGetSymbolAddress((void**)&s8,   g_s8);
    cudaGetSymbolAddress((void**)&t,    g_t);
    cudaGetSymbolAddress((void**)&cur,  g_cur);
    cudaGetSymbolAddress((void**)&te,   g_te);
    cudaGetSymbolAddress((void**)&ddih, g_ddih);
    cudaGetSymbolAddress((void**)&w1h,  g_w1h);
    cudaGetSymbolAddress((void**)&gates,g_gates);
    cudaGetSymbolAddress((void**)&hid,  g_hid);
    cudaGetSymbolAddress((void**)&w2p,  g_w2p);

    float* out = (float*)d_out;

    // 0) merged prep (independent of everything else; also zeros out)
    {
        int total = N_W1 + N_W2 + out_size;
        prep_kernel<<<(total + 255) / 256, 256>>>(ew1, w1h, ew2, w2p, out, out_size);
    }

    // 1) bn + transpose -> h (B,C,L)
    {
        dim3 tb(32, 8);
        dim3 tg((L_ + 31) / 32, (C_ + 31) / 32, B_);
        bn_transpose_kernel<<<tg, tb>>>(x, mdw, mdb, h);
    }
    // 2) fused pools (one pass)
    pool_all_kernel<<<(NROW * 42 + 255) / 256, 256>>>(h, s2, s4, s8);

    // 3) mixer stages (fp32, 64x64 tiles)
    auto mgrid = [](int M, int N) { return dim3((N + 63) / 64, (M + 63) / 64); };
    gemm_m<1><<<mgrid(NROW, 42), 256>>>(s8, 42, w1s[0], b1s[0], nullptr, t,   42,  NROW, 42,  42);
    gemm_m<0><<<mgrid(NROW, 84), 256>>>(t,  42, w2s[0], b2s[0], s4,      cur, 84,  NROW, 84,  42);
    gemm_m<1><<<mgrid(NROW, 84), 256>>>(cur,84, w1s[1], b1s[1], nullptr, t,   84,  NROW, 84,  84);
    gemm_m<0><<<mgrid(NROW,168), 256>>>(t,  84, w2s[1], b2s[1], s2,      cur, 168, NROW, 168, 84);
    gemm_m<1><<<mgrid(NROW,168), 256>>>(cur,168,w1s[2], b1s[2], nullptr, t,   168, NROW, 168, 168);
    gemm_m<0><<<mgrid(NROW,336), 256>>>(t,  168,w2s[2], b2s[2], h,       te,  336, NROW, 336, 168);

    // 4) gating from te
    gate_kernel<<<(NROW * 32 + 255) / 256, 256>>>(te, gw, gb, gates);

    // 5) fused bn+scan (16 lanes/row), emits fp16 ddi
    ddi_scan2_kernel<<<(NROW * 16 + 255) / 256, 256>>>(te, ddw, ddb, n1w, n1b, aggw, aggb, ddih);

    // 6) experts — fp16 m16n8k16, 3-stage cp.async pipeline
    {
        dim3 tg(H_ / 128, (NROW + 127) / 128, E_);
        gemm_f16_l1<<<tg, 256>>>(ddih, w1h, eb1, gates, hid, NROW);
    }
    {
        dim3 tg(1, (NROW + 127) / 128, 8);
        gemm_f16_l2<<<tg, 256>>>(hid, w2p, eb2, gates, out, NROW);
    }
}